// round 1
// baseline (speedup 1.0000x reference)
#include <cuda_runtime.h>
#include <cuda_fp16.h>
#include <mma.h>
#include <math.h>

using namespace nvcuda;

#define HEADS   16
#define DK      64
#define DMODEL  1024
#define NQ      1024
#define BATCH   8
#define MSLOT   8
#define NKV     1032      // real keys + memory slots
#define NKV_PAD 1088      // padded to 17 * 64
#define ROWS    (NQ * BATCH)

// ------------------------- device scratch (no allocs allowed) ---------------
__device__ __half g_q[(size_t)BATCH * HEADS * NQ * DK];        // (b,h,n,dk)
__device__ __half g_k[(size_t)BATCH * HEADS * NKV_PAD * DK];   // (b,h,n,dk) padded
__device__ __half g_v[(size_t)BATCH * HEADS * NKV_PAD * DK];
__device__ float  g_ao[(size_t)ROWS * DMODEL];                 // rows = b*NQ + n

// ------------------------- memory slot / pad fill ---------------------------
__global__ void fill_mem_kernel(const float* __restrict__ m_k,
                                const float* __restrict__ m_v) {
    int idx = blockIdx.x * blockDim.x + threadIdx.x;  // B*H*64*DK = 524288
    if (idx >= BATCH * HEADS * 64 * DK) return;
    int d = idx & 63;
    int s = (idx >> 6) & 63;
    int h = (idx >> 12) & 15;
    int b = idx >> 16;
    size_t o = (((size_t)(b * HEADS + h)) * NKV_PAD + 1024 + s) * DK + d;
    if (s < MSLOT) {
        // mk = sqrt(DK*H)=32 * m_k ; mv = sqrt(M)=2.828427 * m_v  (broadcast over b)
        g_k[o] = __float2half_rn(32.0f * m_k[s * DMODEL + h * 64 + d]);
        g_v[o] = __float2half_rn(2.8284271247461903f * m_v[s * DMODEL + h * 64 + d]);
    } else {
        g_k[o] = __float2half_rn(0.0f);
        g_v[o] = __float2half_rn(0.0f);
    }
}

// ------------------------- QKV projection GEMM ------------------------------
// C = A(f32, split hi/lo fp16) @ W^T(exact fp16) + fp16(bias)
// A rows r = n*BATCH + b ; output scattered to (b,h,n,dk) fp16 scratch.
#define BM 128
#define BN 128
#define BK 32
#define APITCH 40  // half pitch, multiple of 8

__global__ void __launch_bounds__(256) proj_kernel(
    const float* __restrict__ qin, const float* __restrict__ kin,
    const float* __restrict__ vin, const float* __restrict__ w,
    const float* __restrict__ bias) {
    __shared__ __half Ah[BM][APITCH];
    __shared__ __half Al[BM][APITCH];
    __shared__ __half Bs[BN][APITCH];

    const int z = blockIdx.z;
    const float* A = (z == 0) ? qin : ((z == 1) ? kin : vin);
    const float* W = w + (size_t)z * DMODEL * DMODEL;
    __half* dst = (z == 0) ? g_q : ((z == 1) ? g_k : g_v);
    const int L = (z == 0) ? NQ : NKV_PAD;

    const int tid = threadIdx.x;
    const int warp = tid >> 5, lane = tid & 31;
    const int wr = (warp >> 1) * 32, wc = (warp & 1) * 64;
    const int rowbase = blockIdx.y * BM;
    const int colbase = blockIdx.x * BN;

    wmma::fragment<wmma::accumulator, 16, 16, 16, float> acc[2][4];
#pragma unroll
    for (int i = 0; i < 2; i++)
#pragma unroll
        for (int j = 0; j < 4; j++) wmma::fill_fragment(acc[i][j], 0.0f);

    for (int k0 = 0; k0 < DMODEL; k0 += BK) {
#pragma unroll
        for (int it = 0; it < 4; it++) {
            int idx4 = tid + it * 256;          // 1024 float4 total
            int row = idx4 >> 3;
            int c = (idx4 & 7) * 4;
            float4 av = *(const float4*)&A[(size_t)(rowbase + row) * DMODEL + k0 + c];
            __half h0 = __float2half_rn(av.x), h1 = __float2half_rn(av.y);
            __half h2 = __float2half_rn(av.z), h3 = __float2half_rn(av.w);
            Ah[row][c] = h0; Ah[row][c + 1] = h1;
            Ah[row][c + 2] = h2; Ah[row][c + 3] = h3;
            Al[row][c]     = __float2half_rn(av.x - __half2float(h0));
            Al[row][c + 1] = __float2half_rn(av.y - __half2float(h1));
            Al[row][c + 2] = __float2half_rn(av.z - __half2float(h2));
            Al[row][c + 3] = __float2half_rn(av.w - __half2float(h3));
            float4 bv = *(const float4*)&W[(size_t)(colbase + row) * DMODEL + k0 + c];
            Bs[row][c]     = __float2half_rn(bv.x);
            Bs[row][c + 1] = __float2half_rn(bv.y);
            Bs[row][c + 2] = __float2half_rn(bv.z);
            Bs[row][c + 3] = __float2half_rn(bv.w);
        }
        __syncthreads();
#pragma unroll
        for (int kk = 0; kk < 2; kk++) {
            wmma::fragment<wmma::matrix_a, 16, 16, 16, __half, wmma::row_major> fah[2], fal[2];
#pragma unroll
            for (int i = 0; i < 2; i++) {
                wmma::load_matrix_sync(fah[i], &Ah[wr + i * 16][kk * 16], APITCH);
                wmma::load_matrix_sync(fal[i], &Al[wr + i * 16][kk * 16], APITCH);
            }
#pragma unroll
            for (int j = 0; j < 4; j++) {
                wmma::fragment<wmma::matrix_b, 16, 16, 16, __half, wmma::col_major> fb;
                wmma::load_matrix_sync(fb, &Bs[wc + j * 16][kk * 16], APITCH);
#pragma unroll
                for (int i = 0; i < 2; i++) {
                    wmma::mma_sync(acc[i][j], fah[i], fb, acc[i][j]);
                    wmma::mma_sync(acc[i][j], fal[i], fb, acc[i][j]);
                }
            }
        }
        __syncthreads();
    }

    // epilogue: stage each 16x16 frag in (reused) smem, scatter with remap
    float* ep = ((float*)&Ah[0][0]) + warp * 256;
#pragma unroll
    for (int i = 0; i < 2; i++)
#pragma unroll
        for (int j = 0; j < 4; j++) {
            wmma::store_matrix_sync(ep, acc[i][j], 16, wmma::mem_row_major);
            __syncwarp();
            int gr0 = rowbase + wr + i * 16;
            int gc0 = colbase + wc + j * 16;
#pragma unroll
            for (int t = 0; t < 8; t++) {
                int idx = lane + t * 32;
                int r = idx >> 4, c = idx & 15;
                int gr = gr0 + r, gc = gc0 + c;
                float val = ep[idx] +
                            __half2float(__float2half_rn(bias[z * DMODEL + gc]));
                int n = gr >> 3, bb = gr & 7, hh = gc >> 6, d = gc & 63;
                dst[(((size_t)(bb * HEADS + hh)) * L + n) * DK + d] =
                    __float2half_rn(val);
            }
            __syncwarp();
        }
}

// ------------------------- flash attention ---------------------------------
// grid (16 q-tiles, 128 b*h). Block 256 thr (8 warps). Q tile 64 x 64.
static constexpr int ATTN_SMEM = 4 * (64 * 72) * 2 + 2 * (64 * 68) * 4 + 2 * 64 * 4;

__global__ void __launch_bounds__(256) attn_kernel(const float* __restrict__ mask) {
    extern __shared__ __align__(16) char sm[];
    __half* Qs = (__half*)sm;          // 64 x 72
    __half* Ks = Qs + 64 * 72;
    __half* Vs = Ks + 64 * 72;
    __half* Ps = Vs + 64 * 72;
    float* Ss = (float*)(Ps + 64 * 72);  // 64 x 68
    float* Os = Ss + 64 * 68;            // 64 x 68
    float* m_i = Os + 64 * 68;
    float* l_i = m_i + 64;

    const int tid = threadIdx.x;
    const int warp = tid >> 5, lane = tid & 31;
    const int qt = blockIdx.x, bh = blockIdx.y;
    const int q0 = qt * 64;
    const __half* qg = g_q + ((size_t)bh * NQ + q0) * DK;
    const __half* kg = g_k + (size_t)bh * NKV_PAD * DK;
    const __half* vg = g_v + (size_t)bh * NKV_PAD * DK;
    const float* mrow = mask + ((size_t)bh * NQ + q0) * NQ;

#pragma unroll
    for (int it = 0; it < 2; it++) {
        int idx = tid + it * 256;  // 512 uint4
        int row = idx >> 3, c8 = (idx & 7) * 8;
        *(uint4*)&Qs[row * 72 + c8] = *(const uint4*)&qg[row * 64 + c8];
    }
    for (int i = tid; i < 64 * 68; i += 256) Os[i] = 0.0f;
    if (tid < 64) { m_i[tid] = -1e30f; l_i[tid] = 0.0f; }
    __syncthreads();

    const int wr = (warp >> 1) * 16, wc = (warp & 1) * 32;

    for (int t = 0; t < 17; t++) {
        const int kv0 = t * 64;
#pragma unroll
        for (int it = 0; it < 2; it++) {
            int idx = tid + it * 256;
            int row = idx >> 3, c8 = (idx & 7) * 8;
            *(uint4*)&Ks[row * 72 + c8] = *(const uint4*)&kg[(kv0 + row) * 64 + c8];
            *(uint4*)&Vs[row * 72 + c8] = *(const uint4*)&vg[(kv0 + row) * 64 + c8];
        }
        __syncthreads();

        // S = Q @ K^T  (each warp: 16 x 32)
        {
            wmma::fragment<wmma::accumulator, 16, 16, 16, float> sacc[2];
            wmma::fill_fragment(sacc[0], 0.0f);
            wmma::fill_fragment(sacc[1], 0.0f);
#pragma unroll
            for (int kk = 0; kk < 4; kk++) {
                wmma::fragment<wmma::matrix_a, 16, 16, 16, __half, wmma::row_major> fa;
                wmma::load_matrix_sync(fa, &Qs[wr * 72 + kk * 16], 72);
#pragma unroll
                for (int j = 0; j < 2; j++) {
                    wmma::fragment<wmma::matrix_b, 16, 16, 16, __half, wmma::col_major> fb;
                    wmma::load_matrix_sync(fb, &Ks[(wc + j * 16) * 72 + kk * 16], 72);
                    wmma::mma_sync(sacc[j], fa, fb, sacc[j]);
                }
            }
#pragma unroll
            for (int j = 0; j < 2; j++)
                wmma::store_matrix_sync(&Ss[wr * 68 + wc + j * 16], sacc[j], 68,
                                        wmma::mem_row_major);
        }
        __syncthreads();

        // online softmax: warp owns rows [warp*8, warp*8+8)
#pragma unroll
        for (int rr = 0; rr < 8; rr++) {
            int row = warp * 8 + rr;
            int c0 = lane * 2;
            int kvg = kv0 + c0;
            float s0, s1;
            float b0 = Ss[row * 68 + c0] * 0.125f;
            float b1 = Ss[row * 68 + c0 + 1] * 0.125f;
            if (kvg < 1024) {  // kvg even -> kvg+1 < 1024 too
                float2 mm = *(const float2*)&mrow[(size_t)row * NQ + kvg];
                s0 = b0 + mm.x;
                s1 = b1 + mm.y;
            } else {  // memory slots (mask 0) or padding (-inf)
                s0 = (kvg < NKV) ? b0 : -1e30f;
                s1 = (kvg + 1 < NKV) ? b1 : -1e30f;
            }
            float tmax = fmaxf(s0, s1);
#pragma unroll
            for (int o = 16; o; o >>= 1)
                tmax = fmaxf(tmax, __shfl_xor_sync(0xffffffffu, tmax, o));
            float mo = m_i[row];
            float mn = fmaxf(mo, tmax);
            float alpha = __expf(mo - mn);
            float p0 = __expf(s0 - mn), p1 = __expf(s1 - mn);
            float rs = p0 + p1;
#pragma unroll
            for (int o = 16; o; o >>= 1) rs += __shfl_xor_sync(0xffffffffu, rs, o);
            if (lane == 0) {
                l_i[row] = l_i[row] * alpha + rs;
                m_i[row] = mn;
            }
            Ps[row * 72 + c0] = __float2half_rn(p0);
            Ps[row * 72 + c0 + 1] = __float2half_rn(p1);
            Os[row * 68 + c0] *= alpha;
            Os[row * 68 + c0 + 1] *= alpha;
        }
        __syncthreads();

        // O += P @ V (each warp: 16 x 32, accumulator round-trips through smem)
        {
            wmma::fragment<wmma::accumulator, 16, 16, 16, float> oacc[2];
#pragma unroll
            for (int j = 0; j < 2; j++)
                wmma::load_matrix_sync(oacc[j], &Os[wr * 68 + wc + j * 16], 68,
                                       wmma::mem_row_major);
#pragma unroll
            for (int kk = 0; kk < 4; kk++) {
                wmma::fragment<wmma::matrix_a, 16, 16, 16, __half, wmma::row_major> fa;
                wmma::load_matrix_sync(fa, &Ps[wr * 72 + kk * 16], 72);
#pragma unroll
                for (int j = 0; j < 2; j++) {
                    wmma::fragment<wmma::matrix_b, 16, 16, 16, __half, wmma::row_major> fb;
                    wmma::load_matrix_sync(fb, &Vs[(kk * 16) * 72 + wc + j * 16], 72);
                    wmma::mma_sync(oacc[j], fa, fb, oacc[j]);
                }
            }
#pragma unroll
            for (int j = 0; j < 2; j++)
                wmma::store_matrix_sync(&Os[wr * 68 + wc + j * 16], oacc[j], 68,
                                        wmma::mem_row_major);
        }
        __syncthreads();
    }

    // finalize: O /= l, write f32 to g_ao at rows (b*NQ + n), cols h*64 + dk
    const int b = bh >> 4, h = bh & 15;
#pragma unroll
    for (int rr = 0; rr < 8; rr++) {
        int row = warp * 8 + rr;
        float inv = 1.0f / l_i[row];
        int c0 = lane * 2;
        float2 o2 = make_float2(Os[row * 68 + c0] * inv, Os[row * 68 + c0 + 1] * inv);
        *(float2*)&g_ao[((size_t)b * NQ + q0 + row) * DMODEL + h * 64 + c0] = o2;
    }
}

// ------------------------- out projection (split-split) ---------------------
__global__ void __launch_bounds__(256) outproj_kernel(
    const float* __restrict__ w, const float* __restrict__ bias,
    float* __restrict__ out) {
    __shared__ __half Ah[BM][APITCH];
    __shared__ __half Al[BM][APITCH];
    __shared__ __half Bh[BN][APITCH];
    __shared__ __half Bl[BN][APITCH];

    const int tid = threadIdx.x;
    const int warp = tid >> 5, lane = tid & 31;
    const int wr = (warp >> 1) * 32, wc = (warp & 1) * 64;
    const int rowbase = blockIdx.y * BM;
    const int colbase = blockIdx.x * BN;

    wmma::fragment<wmma::accumulator, 16, 16, 16, float> acc[2][4];
#pragma unroll
    for (int i = 0; i < 2; i++)
#pragma unroll
        for (int j = 0; j < 4; j++) wmma::fill_fragment(acc[i][j], 0.0f);

    for (int k0 = 0; k0 < DMODEL; k0 += BK) {
#pragma unroll
        for (int it = 0; it < 4; it++) {
            int idx4 = tid + it * 256;
            int row = idx4 >> 3;
            int c = (idx4 & 7) * 4;
            float4 av = *(const float4*)&g_ao[(size_t)(rowbase + row) * DMODEL + k0 + c];
            __half h0 = __float2half_rn(av.x), h1 = __float2half_rn(av.y);
            __half h2 = __float2half_rn(av.z), h3 = __float2half_rn(av.w);
            Ah[row][c] = h0; Ah[row][c + 1] = h1;
            Ah[row][c + 2] = h2; Ah[row][c + 3] = h3;
            Al[row][c]     = __float2half_rn(av.x - __half2float(h0));
            Al[row][c + 1] = __float2half_rn(av.y - __half2float(h1));
            Al[row][c + 2] = __float2half_rn(av.z - __half2float(h2));
            Al[row][c + 3] = __float2half_rn(av.w - __half2float(h3));
            float4 bv = *(const float4*)&w[(size_t)(colbase + row) * DMODEL + k0 + c];
            __half g0 = __float2half_rn(bv.x), g1 = __float2half_rn(bv.y);
            __half g2 = __float2half_rn(bv.z), g3 = __float2half_rn(bv.w);
            Bh[row][c] = g0; Bh[row][c + 1] = g1;
            Bh[row][c + 2] = g2; Bh[row][c + 3] = g3;
            Bl[row][c]     = __float2half_rn(bv.x - __half2float(g0));
            Bl[row][c + 1] = __float2half_rn(bv.y - __half2float(g1));
            Bl[row][c + 2] = __float2half_rn(bv.z - __half2float(g2));
            Bl[row][c + 3] = __float2half_rn(bv.w - __half2float(g3));
        }
        __syncthreads();
#pragma unroll
        for (int kk = 0; kk < 2; kk++) {
            wmma::fragment<wmma::matrix_a, 16, 16, 16, __half, wmma::row_major> fah[2], fal[2];
#pragma unroll
            for (int i = 0; i < 2; i++) {
                wmma::load_matrix_sync(fah[i], &Ah[wr + i * 16][kk * 16], APITCH);
                wmma::load_matrix_sync(fal[i], &Al[wr + i * 16][kk * 16], APITCH);
            }
#pragma unroll
            for (int j = 0; j < 4; j++) {
                wmma::fragment<wmma::matrix_b, 16, 16, 16, __half, wmma::col_major> fbh, fbl;
                wmma::load_matrix_sync(fbh, &Bh[wc + j * 16][kk * 16], APITCH);
                wmma::load_matrix_sync(fbl, &Bl[wc + j * 16][kk * 16], APITCH);
#pragma unroll
                for (int i = 0; i < 2; i++) {
                    wmma::mma_sync(acc[i][j], fah[i], fbh, acc[i][j]);
                    wmma::mma_sync(acc[i][j], fal[i], fbh, acc[i][j]);
                    wmma::mma_sync(acc[i][j], fah[i], fbl, acc[i][j]);
                }
            }
        }
        __syncthreads();
    }

    float* ep = ((float*)&Ah[0][0]) + warp * 256;
#pragma unroll
    for (int i = 0; i < 2; i++)
#pragma unroll
        for (int j = 0; j < 4; j++) {
            wmma::store_matrix_sync(ep, acc[i][j], 16, wmma::mem_row_major);
            __syncwarp();
            int gr0 = rowbase + wr + i * 16;
            int gc0 = colbase + wc + j * 16;
#pragma unroll
            for (int t = 0; t < 8; t++) {
                int idx = lane + t * 32;
                int r = idx >> 4, c = idx & 15;
                int gr = gr0 + r, gc = gc0 + c;
                float val = ep[idx] + bias[gc];
                int bb = gr >> 10, n = gr & 1023;  // rows of g_ao: b*NQ + n
                out[((size_t)n * BATCH + bb) * DMODEL + gc] = val;
            }
            __syncwarp();
        }
}

// ------------------------- launch -------------------------------------------
extern "C" void kernel_launch(void* const* d_in, const int* in_sizes, int n_in,
                              void* d_out, int out_size) {
    const float* queries = (const float*)d_in[0];
    const float* keys    = (const float*)d_in[1];
    const float* values  = (const float*)d_in[2];
    const float* m_k     = (const float*)d_in[3];
    const float* m_v     = (const float*)d_in[4];
    const float* mask    = (const float*)d_in[5];
    const float* in_w    = (const float*)d_in[6];
    const float* in_b    = (const float*)d_in[7];
    const float* out_w   = (const float*)d_in[8];
    const float* out_b   = (const float*)d_in[9];
    float* out = (float*)d_out;
    (void)in_sizes; (void)n_in; (void)out_size;

    cudaFuncSetAttribute(attn_kernel, cudaFuncAttributeMaxDynamicSharedMemorySize,
                         ATTN_SMEM);

    fill_mem_kernel<<<2048, 256>>>(m_k, m_v);
    proj_kernel<<<dim3(8, 64, 3), 256>>>(queries, keys, values, in_w, in_b);
    attn_kernel<<<dim3(16, 128), 256, ATTN_SMEM>>>(mask);
    outproj_kernel<<<dim3(8, 64), 256>>>(out_w, out_b, out);
}

// round 3
// speedup vs baseline: 1.0756x; 1.0756x over previous
#include <cuda_runtime.h>
#include <cuda_fp16.h>
#include <mma.h>
#include <math.h>
#include <stdint.h>

using namespace nvcuda;

#define HEADS   16
#define DK      64
#define DMODEL  1024
#define NQ      1024
#define BATCH   8
#define MSLOT   8
#define NKV     1032
#define NKV_PAD 1088
#define ROWS    (NQ * BATCH)

// ------------------------- device scratch (no allocs allowed) ---------------
__device__ __half g_inh[(size_t)3 * ROWS * DMODEL];   // fp16 hi of q/k/v inputs
__device__ __half g_inl[(size_t)3 * ROWS * DMODEL];   // fp16 lo residual
__device__ __half g_wh[(size_t)3 * DMODEL * DMODEL];  // fp16(in_proj_weight)
__device__ __half g_woh[(size_t)DMODEL * DMODEL];     // out_w hi
__device__ __half g_wol[(size_t)DMODEL * DMODEL];     // out_w lo
__device__ __half g_q[(size_t)BATCH * HEADS * NQ * DK];
__device__ __half g_k[(size_t)BATCH * HEADS * NKV_PAD * DK];
__device__ __half g_v[(size_t)BATCH * HEADS * NKV_PAD * DK];
__device__ __half g_aoh[(size_t)ROWS * DMODEL];       // attn out hi (row = n*B+b)
__device__ __half g_aol[(size_t)ROWS * DMODEL];       // attn out lo

// ------------------------- helpers ------------------------------------------
__device__ __forceinline__ uint32_t s2u(const void* p) {
    uint32_t a;
    asm("{ .reg .u64 t; cvta.to.shared.u64 t, %1; cvt.u32.u64 %0, t; }"
        : "=r"(a) : "l"(p));
    return a;
}

__device__ __forceinline__ void cpasync16(uint32_t dst, const void* src) {
    asm volatile("cp.async.cg.shared.global [%0], [%1], 16;"
                 :: "r"(dst), "l"(src));
}

#define LDM_X4(r, addr) \
    asm volatile("ldmatrix.sync.aligned.m8n8.x4.shared.b16 {%0,%1,%2,%3}, [%4];" \
                 : "=r"((r)[0]), "=r"((r)[1]), "=r"((r)[2]), "=r"((r)[3]) \
                 : "r"(addr))

__device__ __forceinline__ void mma16816(float* c, const uint32_t* a,
                                         uint32_t b0, uint32_t b1) {
    asm volatile(
        "mma.sync.aligned.m16n8k16.row.col.f32.f16.f16.f32 "
        "{%0,%1,%2,%3}, {%4,%5,%6,%7}, {%8,%9}, {%0,%1,%2,%3};"
        : "+f"(c[0]), "+f"(c[1]), "+f"(c[2]), "+f"(c[3])
        : "r"(a[0]), "r"(a[1]), "r"(a[2]), "r"(a[3]), "r"(b0), "r"(b1));
}

// ------------------------- conversion prepass -------------------------------
__global__ void convert_kernel(const float* __restrict__ q, const float* __restrict__ k,
                               const float* __restrict__ v, const float* __restrict__ wi,
                               const float* __restrict__ wo) {
    size_t i = (size_t)blockIdx.x * blockDim.x + threadIdx.x;
    const size_t NIN = 2097152;   // float4 per input tensor (8192*1024/4)
    if (i < 3 * NIN) {
        int which = (int)(i / NIN);
        size_t off = (i - (size_t)which * NIN) * 4;
        const float* s = (which == 0) ? q : (which == 1) ? k : v;
        float4 f = *(const float4*)(s + off);
        __half h0 = __float2half_rn(f.x), h1 = __float2half_rn(f.y);
        __half h2 = __float2half_rn(f.z), h3 = __float2half_rn(f.w);
        __half hv[4] = {h0, h1, h2, h3};
        __half lv[4] = {__float2half_rn(f.x - __half2float(h0)),
                        __float2half_rn(f.y - __half2float(h1)),
                        __float2half_rn(f.z - __half2float(h2)),
                        __float2half_rn(f.w - __half2float(h3))};
        size_t d = (size_t)which * 8388608 + off;
        *(uint2*)&g_inh[d] = *(uint2*)hv;
        *(uint2*)&g_inl[d] = *(uint2*)lv;
    } else if (i < 3 * NIN + 786432) {
        size_t off = (i - 3 * NIN) * 4;
        float4 f = *(const float4*)(wi + off);
        __half hv[4] = {__float2half_rn(f.x), __float2half_rn(f.y),
                        __float2half_rn(f.z), __float2half_rn(f.w)};
        *(uint2*)&g_wh[off] = *(uint2*)hv;
    } else if (i < 3 * NIN + 786432 + 262144) {
        size_t off = (i - 3 * NIN - 786432) * 4;
        float4 f = *(const float4*)(wo + off);
        __half h0 = __float2half_rn(f.x), h1 = __float2half_rn(f.y);
        __half h2 = __float2half_rn(f.z), h3 = __float2half_rn(f.w);
        __half hv[4] = {h0, h1, h2, h3};
        __half lv[4] = {__float2half_rn(f.x - __half2float(h0)),
                        __float2half_rn(f.y - __half2float(h1)),
                        __float2half_rn(f.z - __half2float(h2)),
                        __float2half_rn(f.w - __half2float(h3))};
        *(uint2*)&g_woh[off] = *(uint2*)hv;
        *(uint2*)&g_wol[off] = *(uint2*)lv;
    }
}

// ------------------------- memory slot / pad fill ---------------------------
__global__ void fill_mem_kernel(const float* __restrict__ m_k,
                                const float* __restrict__ m_v) {
    int idx = blockIdx.x * blockDim.x + threadIdx.x;
    if (idx >= BATCH * HEADS * 64 * DK) return;
    int d = idx & 63;
    int s = (idx >> 6) & 63;
    int h = (idx >> 12) & 15;
    int b = idx >> 16;
    size_t o = (((size_t)(b * HEADS + h)) * NKV_PAD + 1024 + s) * DK + d;
    if (s < MSLOT) {
        g_k[o] = __float2half_rn(32.0f * m_k[s * DMODEL + h * 64 + d]);
        g_v[o] = __float2half_rn(2.8284271247461903f * m_v[s * DMODEL + h * 64 + d]);
    } else {
        g_k[o] = __float2half_rn(0.0f);
        g_v[o] = __float2half_rn(0.0f);
    }
}

// ------------------------- HMMA GEMM (cp.async 4-stage) ---------------------
// C[128x128 tile] = sum over passes of A(pass) @ B(pass)^T, K=1024 per pass.
// EPI 0: QKV proj, passes {Ah*Wh, Al*Wh};  EPI 1: out proj, {Ah*Wh, Al*Wh, Ah*Wl}.
static constexpr int GSTAGES = 4;
static constexpr int A_BYTES = 128 * 80;      // 128 rows x (64B data + 16B pad)
static constexpr int STAGE_B = 2 * A_BYTES;   // A tile + B tile
static constexpr int GEMM_SMEM = GSTAGES * STAGE_B;  // 81920

template <int NT, int EPI>
__global__ void __launch_bounds__(256, 2) gemm_mma(const float* __restrict__ bias,
                                                   float* __restrict__ outp) {
    extern __shared__ __align__(128) char sm[];
    const uint32_t smb = s2u(sm);
    const int tid = threadIdx.x, warp = tid >> 5, lane = tid & 31;
    const int rowbase = blockIdx.y * 128, colbase = blockIdx.x * 128;
    const int wr = (warp >> 2) * 64, wc = (warp & 3) * 32;

    const __half *ah, *al, *bhp, *blp;
    if (EPI == 0) {
        const int z = colbase >> 10;
        ah = g_inh + (size_t)z * 8388608;
        al = g_inl + (size_t)z * 8388608;
        bhp = g_wh; blp = g_wh;
    } else {
        ah = g_aoh; al = g_aol; bhp = g_woh; blp = g_wol;
    }

    float acc[4][4][4];
#pragma unroll
    for (int i = 0; i < 4; i++)
#pragma unroll
        for (int j = 0; j < 4; j++)
#pragma unroll
            for (int u = 0; u < 4; u++) acc[i][j][u] = 0.0f;

    auto issue = [&](int kt) {
        const int slot = kt & 3;
        const int p = kt >> 5;
        const int k0 = (kt & 31) << 5;
        const __half* Ag = ((p == 1) ? al : ah) + (size_t)rowbase * 1024 + k0;
        const __half* Bg = ((p == 2) ? blp : bhp) + (size_t)colbase * 1024 + k0;
        const uint32_t dstA = smb + slot * STAGE_B;
#pragma unroll
        for (int c = 0; c < 4; c++) {
            int idx = tid + c * 256;          // 1024 x 16B chunks
            int isB = idx >> 9;
            int e = idx & 511;
            int r = e >> 2, j = e & 3;
            const __half* src = (isB ? Bg : Ag) + (size_t)r * 1024 + j * 8;
            uint32_t dst = dstA + isB * A_BYTES + r * 80 + j * 16;
            cpasync16(dst, src);
        }
    };

#pragma unroll
    for (int s = 0; s < GSTAGES - 1; s++) {
        issue(s);
        asm volatile("cp.async.commit_group;" ::: "memory");
    }

    for (int kt = 0; kt < NT; kt++) {
        if (kt + GSTAGES - 1 < NT) issue(kt + GSTAGES - 1);
        asm volatile("cp.async.commit_group;" ::: "memory");
        asm volatile("cp.async.wait_group 2;" ::: "memory");
        __syncthreads();

        const uint32_t aBase = smb + (kt & 3) * STAGE_B;
        const uint32_t bBase = aBase + A_BYTES;
#pragma unroll
        for (int k16 = 0; k16 < 2; k16++) {
            uint32_t a[4][4];
#pragma unroll
            for (int mt = 0; mt < 4; mt++) {
                uint32_t addr = aBase + (wr + mt * 16 + (lane & 15)) * 80u +
                                (k16 * 16 + ((lane >> 4) << 3)) * 2u;
                LDM_X4(a[mt], addr);
            }
            uint32_t b[2][4];
#pragma unroll
            for (int bt = 0; bt < 2; bt++) {
                uint32_t addr = bBase +
                                (wc + bt * 16 + (lane & 7) + ((lane >> 4) & 1) * 8) * 80u +
                                (k16 * 16 + ((lane >> 3) & 1) * 8) * 2u;
                LDM_X4(b[bt], addr);
            }
#pragma unroll
            for (int mt = 0; mt < 4; mt++)
#pragma unroll
                for (int nt = 0; nt < 4; nt++)
                    mma16816(acc[mt][nt], a[mt], b[nt >> 1][(nt & 1) * 2],
                             b[nt >> 1][(nt & 1) * 2 + 1]);
        }
        __syncthreads();
    }

    // ------------- epilogue: registers -> global with remap ---------------
    const int r0 = lane >> 2, cp = (lane & 3) * 2;
#pragma unroll
    for (int mt = 0; mt < 4; mt++) {
#pragma unroll
        for (int nt = 0; nt < 4; nt++) {
            const float* cc = acc[mt][nt];
            int gr = rowbase + wr + mt * 16 + r0;
            int gc = colbase + wc + nt * 8 + cp;
            if (EPI == 0) {
                const int z = gc >> 10;
                __half* dst = (z == 0) ? g_q : (z == 1) ? g_k : g_v;
                const int L = (z == 0) ? NQ : NKV_PAD;
                float b0 = __half2float(__float2half_rn(bias[gc]));
                float b1 = __half2float(__float2half_rn(bias[gc + 1]));
                int cz = gc & 1023;
                int hh = cz >> 6, dk = cz & 63;
#pragma unroll
                for (int rh = 0; rh < 2; rh++) {
                    int g = gr + rh * 8;
                    int n = g >> 3, bb = g & 7;
                    size_t o = (((size_t)(bb * HEADS + hh)) * L + n) * 64 + dk;
                    __half hv[2] = {__float2half_rn(cc[rh * 2] + b0),
                                    __float2half_rn(cc[rh * 2 + 1] + b1)};
                    *(uint32_t*)&dst[o] = *(uint32_t*)hv;
                }
            } else {
                float b0 = bias[gc], b1 = bias[gc + 1];
#pragma unroll
                for (int rh = 0; rh < 2; rh++) {
                    int g = gr + rh * 8;
                    float2 v = make_float2(cc[rh * 2] + b0, cc[rh * 2 + 1] + b1);
                    *(float2*)&outp[(size_t)g * 1024 + gc] = v;
                }
            }
        }
    }
}

// ------------------------- flash attention (wmma) ---------------------------
static constexpr int ATTN_SMEM = 4 * (64 * 72) * 2 + 2 * (64 * 68) * 4 + 2 * 64 * 4;

__global__ void __launch_bounds__(256) attn_kernel(const float* __restrict__ mask) {
    extern __shared__ __align__(16) char smc[];
    __half* Qs = (__half*)smc;  // 64 x 72
    __half* Ks = Qs + 64 * 72;
    __half* Vs = Ks + 64 * 72;
    __half* Ps = Vs + 64 * 72;
    float* Ss = (float*)(Ps + 64 * 72);  // 64 x 68
    float* Os = Ss + 64 * 68;
    float* m_i = Os + 64 * 68;
    float* l_i = m_i + 64;

    const int tid = threadIdx.x;
    const int warp = tid >> 5, lane = tid & 31;
    const int qt = blockIdx.x, bh = blockIdx.y;
    const int q0 = qt * 64;
    const __half* qg = g_q + ((size_t)bh * NQ + q0) * DK;
    const __half* kg = g_k + (size_t)bh * NKV_PAD * DK;
    const __half* vg = g_v + (size_t)bh * NKV_PAD * DK;
    const float* mrow = mask + ((size_t)bh * NQ + q0) * NQ;

#pragma unroll
    for (int it = 0; it < 2; it++) {
        int idx = tid + it * 256;
        int row = idx >> 3, c8 = (idx & 7) * 8;
        *(uint4*)&Qs[row * 72 + c8] = *(const uint4*)&qg[row * 64 + c8];
    }
    for (int i = tid; i < 64 * 68; i += 256) Os[i] = 0.0f;
    if (tid < 64) { m_i[tid] = -1e30f; l_i[tid] = 0.0f; }
    __syncthreads();

    const int wr = (warp >> 1) * 16, wc = (warp & 1) * 32;

    for (int t = 0; t < 17; t++) {
        const int kv0 = t * 64;
#pragma unroll
        for (int it = 0; it < 2; it++) {
            int idx = tid + it * 256;
            int row = idx >> 3, c8 = (idx & 7) * 8;
            *(uint4*)&Ks[row * 72 + c8] = *(const uint4*)&kg[(kv0 + row) * 64 + c8];
            *(uint4*)&Vs[row * 72 + c8] = *(const uint4*)&vg[(kv0 + row) * 64 + c8];
        }
        __syncthreads();

        {
            wmma::fragment<wmma::accumulator, 16, 16, 16, float> sacc[2];
            wmma::fill_fragment(sacc[0], 0.0f);
            wmma::fill_fragment(sacc[1], 0.0f);
#pragma unroll
            for (int kk = 0; kk < 4; kk++) {
                wmma::fragment<wmma::matrix_a, 16, 16, 16, __half, wmma::row_major> fa;
                wmma::load_matrix_sync(fa, &Qs[wr * 72 + kk * 16], 72);
#pragma unroll
                for (int j = 0; j < 2; j++) {
                    wmma::fragment<wmma::matrix_b, 16, 16, 16, __half, wmma::col_major> fb;
                    wmma::load_matrix_sync(fb, &Ks[(wc + j * 16) * 72 + kk * 16], 72);
                    wmma::mma_sync(sacc[j], fa, fb, sacc[j]);
                }
            }
#pragma unroll
            for (int j = 0; j < 2; j++)
                wmma::store_matrix_sync(&Ss[wr * 68 + wc + j * 16], sacc[j], 68,
                                        wmma::mem_row_major);
        }
        __syncthreads();

#pragma unroll
        for (int rr = 0; rr < 8; rr++) {
            int row = warp * 8 + rr;
            int c0 = lane * 2;
            int kvg = kv0 + c0;
            float s0, s1;
            float b0 = Ss[row * 68 + c0] * 0.125f;
            float b1 = Ss[row * 68 + c0 + 1] * 0.125f;
            if (kvg < 1024) {
                float2 mm = *(const float2*)&mrow[(size_t)row * NQ + kvg];
                s0 = b0 + mm.x;
                s1 = b1 + mm.y;
            } else {
                s0 = (kvg < NKV) ? b0 : -1e30f;
                s1 = (kvg + 1 < NKV) ? b1 : -1e30f;
            }
            float tmax = fmaxf(s0, s1);
#pragma unroll
            for (int o = 16; o; o >>= 1)
                tmax = fmaxf(tmax, __shfl_xor_sync(0xffffffffu, tmax, o));
            float mo = m_i[row];
            float mn = fmaxf(mo, tmax);
            float alpha = __expf(mo - mn);
            float p0 = __expf(s0 - mn), p1 = __expf(s1 - mn);
            float rs = p0 + p1;
#pragma unroll
            for (int o = 16; o; o >>= 1) rs += __shfl_xor_sync(0xffffffffu, rs, o);
            if (lane == 0) {
                l_i[row] = l_i[row] * alpha + rs;
                m_i[row] = mn;
            }
            Ps[row * 72 + c0] = __float2half_rn(p0);
            Ps[row * 72 + c0 + 1] = __float2half_rn(p1);
            Os[row * 68 + c0] *= alpha;
            Os[row * 68 + c0 + 1] *= alpha;
        }
        __syncthreads();

        {
            wmma::fragment<wmma::accumulator, 16, 16, 16, float> oacc[2];
#pragma unroll
            for (int j = 0; j < 2; j++)
                wmma::load_matrix_sync(oacc[j], &Os[wr * 68 + wc + j * 16], 68,
                                       wmma::mem_row_major);
#pragma unroll
            for (int kk = 0; kk < 4; kk++) {
                wmma::fragment<wmma::matrix_a, 16, 16, 16, __half, wmma::row_major> fa;
                wmma::load_matrix_sync(fa, &Ps[wr * 72 + kk * 16], 72);
#pragma unroll
                for (int j = 0; j < 2; j++) {
                    wmma::fragment<wmma::matrix_b, 16, 16, 16, __half, wmma::row_major> fb;
                    wmma::load_matrix_sync(fb, &Vs[(kk * 16) * 72 + wc + j * 16], 72);
                    wmma::mma_sync(oacc[j], fa, fb, oacc[j]);
                }
            }
#pragma unroll
            for (int j = 0; j < 2; j++)
                wmma::store_matrix_sync(&Os[wr * 68 + wc + j * 16], oacc[j], 68,
                                        wmma::mem_row_major);
        }
        __syncthreads();
    }

    const int b = bh >> 4, h = bh & 15;
#pragma unroll
    for (int rr = 0; rr < 8; rr++) {
        int row = warp * 8 + rr;
        float inv = 1.0f / l_i[row];
        int c0 = lane * 2;
        float o0 = Os[row * 68 + c0] * inv;
        float o1 = Os[row * 68 + c0 + 1] * inv;
        __half h0 = __float2half_rn(o0), h1 = __float2half_rn(o1);
        __half e0 = __float2half_rn(o0 - __half2float(h0));
        __half e1 = __float2half_rn(o1 - __half2float(h1));
        size_t off = ((size_t)(q0 + row) * BATCH + b) * DMODEL + h * 64 + c0;
        __half hv[2] = {h0, h1};
        __half lv[2] = {e0, e1};
        *(uint32_t*)&g_aoh[off] = *(uint32_t*)hv;
        *(uint32_t*)&g_aol[off] = *(uint32_t*)lv;
    }
}

// ------------------------- launch -------------------------------------------
extern "C" void kernel_launch(void* const* d_in, const int* in_sizes, int n_in,
                              void* d_out, int out_size) {
    const float* queries = (const float*)d_in[0];
    const float* keys    = (const float*)d_in[1];
    const float* values  = (const float*)d_in[2];
    const float* m_k     = (const float*)d_in[3];
    const float* m_v     = (const float*)d_in[4];
    const float* mask    = (const float*)d_in[5];
    const float* in_w    = (const float*)d_in[6];
    const float* in_b    = (const float*)d_in[7];
    const float* out_w   = (const float*)d_in[8];
    const float* out_b   = (const float*)d_in[9];
    float* out = (float*)d_out;
    (void)in_sizes; (void)n_in; (void)out_size;

    cudaFuncSetAttribute(attn_kernel, cudaFuncAttributeMaxDynamicSharedMemorySize,
                         ATTN_SMEM);
    cudaFuncSetAttribute(gemm_mma<64, 0>, cudaFuncAttributeMaxDynamicSharedMemorySize,
                         GEMM_SMEM);
    cudaFuncSetAttribute(gemm_mma<96, 1>, cudaFuncAttributeMaxDynamicSharedMemorySize,
                         GEMM_SMEM);

    convert_kernel<<<28672, 256>>>(queries, keys, values, in_w, out_w);
    fill_mem_kernel<<<2048, 256>>>(m_k, m_v);
    gemm_mma<64, 0><<<dim3(24, 64), 256, GEMM_SMEM>>>(in_b, nullptr);  // QKV proj
    attn_kernel<<<dim3(16, 128), 256, ATTN_SMEM>>>(mask);
    gemm_mma<96, 1><<<dim3(8, 64), 256, GEMM_SMEM>>>(out_b, out);      // out proj
}

// round 5
// speedup vs baseline: 1.5121x; 1.4057x over previous
#include <cuda_runtime.h>
#include <cuda_fp16.h>
#include <math.h>
#include <stdint.h>

#define HEADS   16
#define DK      64
#define DMODEL  1024
#define NQ      1024
#define BATCH   8
#define MSLOT   8
#define NKV     1032
#define NKV_PAD 1088
#define ROWS    (NQ * BATCH)

// ------------------------- device scratch (no allocs allowed) ---------------
__device__ __half g_inh[(size_t)3 * ROWS * DMODEL];   // fp16 hi of q/k/v inputs
__device__ __half g_inl[(size_t)3 * ROWS * DMODEL];   // fp16 lo residual
__device__ __half g_wh[(size_t)3 * DMODEL * DMODEL];  // fp16(in_proj_weight)
__device__ __half g_woh[(size_t)DMODEL * DMODEL];     // out_w hi
__device__ __half g_wol[(size_t)DMODEL * DMODEL];     // out_w lo
__device__ __half g_q[(size_t)BATCH * HEADS * NQ * DK];
__device__ __half g_k[(size_t)BATCH * HEADS * NKV_PAD * DK];
__device__ __half g_v[(size_t)BATCH * HEADS * NKV_PAD * DK];
__device__ __half g_aoh[(size_t)ROWS * DMODEL];       // attn out hi (row = n*B+b)
__device__ __half g_aol[(size_t)ROWS * DMODEL];       // attn out lo

// ------------------------- helpers ------------------------------------------
__device__ __forceinline__ uint32_t s2u(const void* p) {
    uint32_t a;
    asm("{ .reg .u64 t; cvta.to.shared.u64 t, %1; cvt.u32.u64 %0, t; }"
        : "=r"(a) : "l"(p));
    return a;
}

__device__ __forceinline__ void cpasync16(uint32_t dst, const void* src) {
    asm volatile("cp.async.cg.shared.global [%0], [%1], 16;"
                 :: "r"(dst), "l"(src));
}

#define LDM_X4(r, addr) \
    asm volatile("ldmatrix.sync.aligned.m8n8.x4.shared.b16 {%0,%1,%2,%3}, [%4];" \
                 : "=r"((r)[0]), "=r"((r)[1]), "=r"((r)[2]), "=r"((r)[3]) \
                 : "r"(addr))

#define LDM_X4_T(r, addr) \
    asm volatile("ldmatrix.sync.aligned.m8n8.x4.trans.shared.b16 {%0,%1,%2,%3}, [%4];" \
                 : "=r"((r)[0]), "=r"((r)[1]), "=r"((r)[2]), "=r"((r)[3]) \
                 : "r"(addr))

__device__ __forceinline__ void mma16816(float* c, const uint32_t* a,
                                         uint32_t b0, uint32_t b1) {
    asm volatile(
        "mma.sync.aligned.m16n8k16.row.col.f32.f16.f16.f32 "
        "{%0,%1,%2,%3}, {%4,%5,%6,%7}, {%8,%9}, {%0,%1,%2,%3};"
        : "+f"(c[0]), "+f"(c[1]), "+f"(c[2]), "+f"(c[3])
        : "r"(a[0]), "r"(a[1]), "r"(a[2]), "r"(a[3]), "r"(b0), "r"(b1));
}

__device__ __forceinline__ uint32_t packh2(float x, float y) {
    __half2 h = __floats2half2_rn(x, y);
    return *(uint32_t*)&h;
}

// ------------------------- conversion prepass -------------------------------
__global__ void convert_kernel(const float* __restrict__ q, const float* __restrict__ k,
                               const float* __restrict__ v, const float* __restrict__ wi,
                               const float* __restrict__ wo) {
    size_t i = (size_t)blockIdx.x * blockDim.x + threadIdx.x;
    const size_t NIN = 2097152;   // float4 per input tensor (8192*1024/4)
    if (i < 3 * NIN) {
        int which = (int)(i / NIN);
        size_t off = (i - (size_t)which * NIN) * 4;
        const float* s = (which == 0) ? q : (which == 1) ? k : v;
        float4 f = *(const float4*)(s + off);
        __half h0 = __float2half_rn(f.x), h1 = __float2half_rn(f.y);
        __half h2 = __float2half_rn(f.z), h3 = __float2half_rn(f.w);
        __half hv[4] = {h0, h1, h2, h3};
        __half lv[4] = {__float2half_rn(f.x - __half2float(h0)),
                        __float2half_rn(f.y - __half2float(h1)),
                        __float2half_rn(f.z - __half2float(h2)),
                        __float2half_rn(f.w - __half2float(h3))};
        size_t d = (size_t)which * 8388608 + off;
        *(uint2*)&g_inh[d] = *(uint2*)hv;
        *(uint2*)&g_inl[d] = *(uint2*)lv;
    } else if (i < 3 * NIN + 786432) {
        size_t off = (i - 3 * NIN) * 4;
        float4 f = *(const float4*)(wi + off);
        __half hv[4] = {__float2half_rn(f.x), __float2half_rn(f.y),
                        __float2half_rn(f.z), __float2half_rn(f.w)};
        *(uint2*)&g_wh[off] = *(uint2*)hv;
    } else if (i < 3 * NIN + 786432 + 262144) {
        size_t off = (i - 3 * NIN - 786432) * 4;
        float4 f = *(const float4*)(wo + off);
        __half h0 = __float2half_rn(f.x), h1 = __float2half_rn(f.y);
        __half h2 = __float2half_rn(f.z), h3 = __float2half_rn(f.w);
        __half hv[4] = {h0, h1, h2, h3};
        __half lv[4] = {__float2half_rn(f.x - __half2float(h0)),
                        __float2half_rn(f.y - __half2float(h1)),
                        __float2half_rn(f.z - __half2float(h2)),
                        __float2half_rn(f.w - __half2float(h3))};
        *(uint2*)&g_woh[off] = *(uint2*)hv;
        *(uint2*)&g_wol[off] = *(uint2*)lv;
    }
}

// ------------------------- memory slot / pad fill ---------------------------
__global__ void fill_mem_kernel(const float* __restrict__ m_k,
                                const float* __restrict__ m_v) {
    int idx = blockIdx.x * blockDim.x + threadIdx.x;
    if (idx >= BATCH * HEADS * 64 * DK) return;
    int d = idx & 63;
    int s = (idx >> 6) & 63;
    int h = (idx >> 12) & 15;
    int b = idx >> 16;
    size_t o = (((size_t)(b * HEADS + h)) * NKV_PAD + 1024 + s) * DK + d;
    if (s < MSLOT) {
        g_k[o] = __float2half_rn(32.0f * m_k[s * DMODEL + h * 64 + d]);
        g_v[o] = __float2half_rn(2.8284271247461903f * m_v[s * DMODEL + h * 64 + d]);
    } else {
        g_k[o] = __float2half_rn(0.0f);
        g_v[o] = __float2half_rn(0.0f);
    }
}

// ------------------------- HMMA GEMM (cp.async 4-stage) ---------------------
static constexpr int GSTAGES = 4;
static constexpr int A_BYTES = 128 * 80;
static constexpr int STAGE_B = 2 * A_BYTES;
static constexpr int GEMM_SMEM = GSTAGES * STAGE_B;  // 81920

template <int NT, int EPI>
__global__ void __launch_bounds__(256, 2) gemm_mma(const float* __restrict__ bias,
                                                   float* __restrict__ outp) {
    extern __shared__ __align__(128) char sm[];
    const uint32_t smb = s2u(sm);
    const int tid = threadIdx.x, warp = tid >> 5, lane = tid & 31;
    const int rowbase = blockIdx.y * 128, colbase = blockIdx.x * 128;
    const int wr = (warp >> 2) * 64, wc = (warp & 3) * 32;

    const __half *ah, *al, *bhp, *blp;
    if (EPI == 0) {
        const int z = colbase >> 10;
        ah = g_inh + (size_t)z * 8388608;
        al = g_inl + (size_t)z * 8388608;
        bhp = g_wh; blp = g_wh;
    } else {
        ah = g_aoh; al = g_aol; bhp = g_woh; blp = g_wol;
    }

    float acc[4][4][4];
#pragma unroll
    for (int i = 0; i < 4; i++)
#pragma unroll
        for (int j = 0; j < 4; j++)
#pragma unroll
            for (int u = 0; u < 4; u++) acc[i][j][u] = 0.0f;

    auto issue = [&](int kt) {
        const int slot = kt & 3;
        const int p = kt >> 5;
        const int k0 = (kt & 31) << 5;
        const __half* Ag = ((p == 1) ? al : ah) + (size_t)rowbase * 1024 + k0;
        const __half* Bg = ((p == 2) ? blp : bhp) + (size_t)colbase * 1024 + k0;
        const uint32_t dstA = smb + slot * STAGE_B;
#pragma unroll
        for (int c = 0; c < 4; c++) {
            int idx = tid + c * 256;
            int isB = idx >> 9;
            int e = idx & 511;
            int r = e >> 2, j = e & 3;
            const __half* src = (isB ? Bg : Ag) + (size_t)r * 1024 + j * 8;
            uint32_t dst = dstA + isB * A_BYTES + r * 80 + j * 16;
            cpasync16(dst, src);
        }
    };

#pragma unroll
    for (int s = 0; s < GSTAGES - 1; s++) {
        issue(s);
        asm volatile("cp.async.commit_group;" ::: "memory");
    }

    for (int kt = 0; kt < NT; kt++) {
        if (kt + GSTAGES - 1 < NT) issue(kt + GSTAGES - 1);
        asm volatile("cp.async.commit_group;" ::: "memory");
        asm volatile("cp.async.wait_group 2;" ::: "memory");
        __syncthreads();

        const uint32_t aBase = smb + (kt & 3) * STAGE_B;
        const uint32_t bBase = aBase + A_BYTES;
#pragma unroll
        for (int k16 = 0; k16 < 2; k16++) {
            uint32_t a[4][4];
#pragma unroll
            for (int mt = 0; mt < 4; mt++) {
                uint32_t addr = aBase + (wr + mt * 16 + (lane & 15)) * 80u +
                                (k16 * 16 + ((lane >> 4) << 3)) * 2u;
                LDM_X4(a[mt], addr);
            }
            uint32_t b[2][4];
#pragma unroll
            for (int bt = 0; bt < 2; bt++) {
                uint32_t addr = bBase +
                                (wc + bt * 16 + (lane & 7) + ((lane >> 4) & 1) * 8) * 80u +
                                (k16 * 16 + ((lane >> 3) & 1) * 8) * 2u;
                LDM_X4(b[bt], addr);
            }
#pragma unroll
            for (int mt = 0; mt < 4; mt++)
#pragma unroll
                for (int nt = 0; nt < 4; nt++)
                    mma16816(acc[mt][nt], a[mt], b[nt >> 1][(nt & 1) * 2],
                             b[nt >> 1][(nt & 1) * 2 + 1]);
        }
        __syncthreads();
    }

    const int r0 = lane >> 2, cp = (lane & 3) * 2;
#pragma unroll
    for (int mt = 0; mt < 4; mt++) {
#pragma unroll
        for (int nt = 0; nt < 4; nt++) {
            const float* cc = acc[mt][nt];
            int gr = rowbase + wr + mt * 16 + r0;
            int gc = colbase + wc + nt * 8 + cp;
            if (EPI == 0) {
                const int z = gc >> 10;
                __half* dst = (z == 0) ? g_q : (z == 1) ? g_k : g_v;
                const int L = (z == 0) ? NQ : NKV_PAD;
                float b0 = __half2float(__float2half_rn(bias[gc]));
                float b1 = __half2float(__float2half_rn(bias[gc + 1]));
                int cz = gc & 1023;
                int hh = cz >> 6, dk = cz & 63;
#pragma unroll
                for (int rh = 0; rh < 2; rh++) {
                    int g = gr + rh * 8;
                    int n = g >> 3, bb = g & 7;
                    size_t o = (((size_t)(bb * HEADS + hh)) * L + n) * 64 + dk;
                    __half hv[2] = {__float2half_rn(cc[rh * 2] + b0),
                                    __float2half_rn(cc[rh * 2 + 1] + b1)};
                    *(uint32_t*)&dst[o] = *(uint32_t*)hv;
                }
            } else {
                float b0 = bias[gc], b1 = bias[gc + 1];
#pragma unroll
                for (int rh = 0; rh < 2; rh++) {
                    int g = gr + rh * 8;
                    float2 v = make_float2(cc[rh * 2] + b0, cc[rh * 2 + 1] + b1);
                    *(float2*)&outp[(size_t)g * 1024 + gc] = v;
                }
            }
        }
    }
}

// ------------------------- flash attention (register-resident FA2) ----------
// Block: 128 q rows, 8 warps x 16 rows. KV tiles of 64, double-buffered cp.async.
static constexpr int ATTN_SMEM = 16384 + 2 * 16384;

__global__ void __launch_bounds__(256, 2) attn_kernel(const float* __restrict__ mask) {
    extern __shared__ __align__(128) char smc[];
    const uint32_t smb = s2u(smc);
    const int tid = threadIdx.x, warp = tid >> 5, lane = tid & 31;
    const int qt = blockIdx.x, bh = blockIdx.y;
    const int q0 = qt * 128;
    const __half* qg = g_q + ((size_t)bh * NQ + q0) * DK;
    const __half* kg = g_k + (size_t)bh * NKV_PAD * DK;
    const __half* vg = g_v + (size_t)bh * NKV_PAD * DK;

    // ---- stage Q (swizzled 16B chunks), then per-warp a-frags scaled 1/8 ----
#pragma unroll
    for (int it = 0; it < 4; it++) {
        int idx = tid + it * 256;           // 1024 chunks
        int r = idx >> 3, c = idx & 7;
        *(uint4*)(smc + r * 128 + ((c ^ (r & 7)) * 16)) =
            *(const uint4*)(qg + (size_t)r * 64 + c * 8);
    }
    __syncthreads();

    uint32_t qa[4][4];
    {
        const __half2 sc8 = __floats2half2_rn(0.125f, 0.125f);
        int r = warp * 16 + (lane & 7) + ((lane >> 3) & 1) * 8;   // A pattern
#pragma unroll
        for (int u = 0; u < 4; u++) {
            int c = u * 2 + (lane >> 4);
            uint32_t addr = smb + r * 128 + ((c ^ (r & 7)) * 16);
            LDM_X4(qa[u], addr);
#pragma unroll
            for (int j = 0; j < 4; j++) {
                __half2 h = __hmul2(*(__half2*)&qa[u][j], sc8);
                qa[u][j] = *(uint32_t*)&h;
            }
        }
    }
    __syncthreads();   // Qs region dead; KV buffers live at +16384

    auto issueKV = [&](int t) {
        const uint32_t base = smb + 16384 + (t & 1) * 16384;
        const __half* kp = kg + (size_t)t * 64 * 64;
        const __half* vp = vg + (size_t)t * 64 * 64;
#pragma unroll
        for (int it = 0; it < 2; it++) {
            int idx = tid + it * 256;       // 512 chunks each
            int r = idx >> 3, c = idx & 7;
            uint32_t so = r * 128 + ((c ^ (r & 7)) * 16);
            cpasync16(base + so, kp + (size_t)r * 64 + c * 8);
            cpasync16(base + 8192 + so, vp + (size_t)r * 64 + c * 8);
        }
    };

    float o[8][4];
#pragma unroll
    for (int n = 0; n < 8; n++)
#pragma unroll
        for (int j = 0; j < 4; j++) o[n][j] = 0.0f;
    float mprevA = -1e30f, mprevB = -1e30f, laccA = 0.0f, laccB = 0.0f;

    const int rA = lane >> 2;
    const float* mrowA = mask + ((size_t)bh * NQ + q0 + warp * 16 + rA) * NQ +
                         2 * (lane & 3);
    const float* mrowB = mrowA + 8 * NQ;

    issueKV(0);
    asm volatile("cp.async.commit_group;" ::: "memory");

    for (int t = 0; t < 17; t++) {
        if (t < 16) {
            issueKV(t + 1);
            asm volatile("cp.async.commit_group;" ::: "memory");
            asm volatile("cp.async.wait_group 1;" ::: "memory");
        } else {
            asm volatile("cp.async.wait_group 0;" ::: "memory");
        }
        __syncthreads();

        const uint32_t kb = smb + 16384 + (t & 1) * 16384;
        const uint32_t vb = kb + 8192;

        // ---- S = (Q/8) @ K^T  (K loaded with B-operand lane pattern) ----
        float s[8][4];
#pragma unroll
        for (int n = 0; n < 8; n++)
#pragma unroll
            for (int j = 0; j < 4; j++) s[n][j] = 0.0f;
        {
            const int rn = (lane & 7) + ((lane >> 4) & 1) * 8;  // n-row offset
            const int ck = (lane >> 3) & 1;                     // k-chunk offset
#pragma unroll
            for (int g = 0; g < 4; g++) {
                int r = g * 16 + rn;
#pragma unroll
                for (int u = 0; u < 4; u++) {
                    int c = u * 2 + ck;
                    uint32_t kb4[4];
                    LDM_X4(kb4, kb + r * 128 + ((c ^ (r & 7)) * 16));
                    // kb4: (n0,k0),(n0,k8),(n8,k0),(n8,k8)
                    mma16816(s[2 * g],     qa[u], kb4[0], kb4[1]);
                    mma16816(s[2 * g + 1], qa[u], kb4[2], kb4[3]);
                }
            }
        }

        // ---- mask ----
        if (t < 16) {
            const float* mA = mrowA + t * 64;
            const float* mB = mrowB + t * 64;
#pragma unroll
            for (int n = 0; n < 8; n++) {
                float2 xa = *(const float2*)(mA + n * 8);
                float2 xb = *(const float2*)(mB + n * 8);
                s[n][0] += xa.x; s[n][1] += xa.y;
                s[n][2] += xb.x; s[n][3] += xb.y;
            }
        } else {
            // keys 1024-1031 (n==0) are memory slots (mask 0); rest padding
#pragma unroll
            for (int n = 1; n < 8; n++) {
                s[n][0] = s[n][1] = s[n][2] = s[n][3] = -1e30f;
            }
        }

        // ---- online softmax (register) ----
        float mxA = -1e30f, mxB = -1e30f;
#pragma unroll
        for (int n = 0; n < 8; n++) {
            mxA = fmaxf(mxA, fmaxf(s[n][0], s[n][1]));
            mxB = fmaxf(mxB, fmaxf(s[n][2], s[n][3]));
        }
        mxA = fmaxf(mxA, __shfl_xor_sync(0xffffffffu, mxA, 1));
        mxA = fmaxf(mxA, __shfl_xor_sync(0xffffffffu, mxA, 2));
        mxB = fmaxf(mxB, __shfl_xor_sync(0xffffffffu, mxB, 1));
        mxB = fmaxf(mxB, __shfl_xor_sync(0xffffffffu, mxB, 2));
        float mnA = fmaxf(mprevA, mxA), mnB = fmaxf(mprevB, mxB);
        float aA = __expf(mprevA - mnA), aB = __expf(mprevB - mnB);
        mprevA = mnA; mprevB = mnB;

        uint32_t pf[4][4];
        float sumA = 0.0f, sumB = 0.0f;
#pragma unroll
        for (int n = 0; n < 8; n++) {
            float p0 = __expf(s[n][0] - mnA);
            float p1 = __expf(s[n][1] - mnA);
            float p2 = __expf(s[n][2] - mnB);
            float p3 = __expf(s[n][3] - mnB);
            sumA += p0 + p1; sumB += p2 + p3;
            pf[n >> 1][(n & 1) * 2]     = packh2(p0, p1);
            pf[n >> 1][(n & 1) * 2 + 1] = packh2(p2, p3);
        }
        sumA += __shfl_xor_sync(0xffffffffu, sumA, 1);
        sumA += __shfl_xor_sync(0xffffffffu, sumA, 2);
        sumB += __shfl_xor_sync(0xffffffffu, sumB, 1);
        sumB += __shfl_xor_sync(0xffffffffu, sumB, 2);
        laccA = laccA * aA + sumA;
        laccB = laccB * aB + sumB;
#pragma unroll
        for (int n = 0; n < 8; n++) {
            o[n][0] *= aA; o[n][1] *= aA;
            o[n][2] *= aB; o[n][3] *= aB;
        }

        // ---- O += P @ V (V trans-loaded; pairing verified) ----
        {
            int rr = (lane & 7) + ((lane >> 3) & 1) * 8;
#pragma unroll
            for (int u = 0; u < 4; u++) {
                int r = u * 16 + rr;
#pragma unroll
                for (int dp = 0; dp < 4; dp++) {
                    int c = dp * 2 + (lane >> 4);
                    uint32_t vb4[4];
                    LDM_X4_T(vb4, vb + r * 128 + ((c ^ (r & 7)) * 16));
                    mma16816(o[2 * dp],     pf[u], vb4[0], vb4[1]);
                    mma16816(o[2 * dp + 1], pf[u], vb4[2], vb4[3]);
                }
            }
        }
        __syncthreads();
    }

    // ---- finalize: O /= l, write fp16 hi/lo to g_aoh/g_aol (row = q*B + b) --
    const int b = bh >> 4, h = bh & 15;
    const int qrA = q0 + warp * 16 + rA;
    const float invA = 1.0f / laccA, invB = 1.0f / laccB;
#pragma unroll
    for (int n = 0; n < 8; n++) {
        int dk = h * 64 + n * 8 + 2 * (lane & 3);
        {
            float o0 = o[n][0] * invA, o1 = o[n][1] * invA;
            __half h0 = __float2half_rn(o0), h1 = __float2half_rn(o1);
            __half e0 = __float2half_rn(o0 - __half2float(h0));
            __half e1 = __float2half_rn(o1 - __half2float(h1));
            size_t off = ((size_t)qrA * BATCH + b) * DMODEL + dk;
            __half hv[2] = {h0, h1};
            __half lv[2] = {e0, e1};
            *(uint32_t*)&g_aoh[off] = *(uint32_t*)hv;
            *(uint32_t*)&g_aol[off] = *(uint32_t*)lv;
        }
        {
            float o0 = o[n][2] * invB, o1 = o[n][3] * invB;
            __half h0 = __float2half_rn(o0), h1 = __float2half_rn(o1);
            __half e0 = __float2half_rn(o0 - __half2float(h0));
            __half e1 = __float2half_rn(o1 - __half2float(h1));
            size_t off = ((size_t)(qrA + 8) * BATCH + b) * DMODEL + dk;
            __half hv[2] = {h0, h1};
            __half lv[2] = {e0, e1};
            *(uint32_t*)&g_aoh[off] = *(uint32_t*)hv;
            *(uint32_t*)&g_aol[off] = *(uint32_t*)lv;
        }
    }
}

// ------------------------- launch -------------------------------------------
extern "C" void kernel_launch(void* const* d_in, const int* in_sizes, int n_in,
                              void* d_out, int out_size) {
    const float* queries = (const float*)d_in[0];
    const float* keys    = (const float*)d_in[1];
    const float* values  = (const float*)d_in[2];
    const float* m_k     = (const float*)d_in[3];
    const float* m_v     = (const float*)d_in[4];
    const float* mask    = (const float*)d_in[5];
    const float* in_w    = (const float*)d_in[6];
    const float* in_b    = (const float*)d_in[7];
    const float* out_w   = (const float*)d_in[8];
    const float* out_b   = (const float*)d_in[9];
    float* out = (float*)d_out;
    (void)in_sizes; (void)n_in; (void)out_size;

    cudaFuncSetAttribute(attn_kernel, cudaFuncAttributeMaxDynamicSharedMemorySize,
                         ATTN_SMEM);
    cudaFuncSetAttribute(gemm_mma<64, 0>, cudaFuncAttributeMaxDynamicSharedMemorySize,
                         GEMM_SMEM);
    cudaFuncSetAttribute(gemm_mma<96, 1>, cudaFuncAttributeMaxDynamicSharedMemorySize,
                         GEMM_SMEM);

    convert_kernel<<<28672, 256>>>(queries, keys, values, in_w, out_w);
    fill_mem_kernel<<<2048, 256>>>(m_k, m_v);
    gemm_mma<64, 0><<<dim3(24, 64), 256, GEMM_SMEM>>>(in_b, nullptr);  // QKV proj
    attn_kernel<<<dim3(8, 128), 256, ATTN_SMEM>>>(mask);
    gemm_mma<96, 1><<<dim3(8, 64), 256, GEMM_SMEM>>>(out_b, out);      // out proj
}

// round 6
// speedup vs baseline: 2.3116x; 1.5288x over previous
#include <cuda_runtime.h>
#include <cuda_fp16.h>
#include <math.h>
#include <stdint.h>

#define HEADS   16
#define DK      64
#define DMODEL  1024
#define NQ      1024
#define BATCH   8
#define MSLOT   8
#define NKV     1032
#define NKV_PAD 1088
#define ROWS    (NQ * BATCH)

// ------------------------- device scratch (no allocs allowed) ---------------
__device__ __half g_inh[(size_t)3 * ROWS * DMODEL];   // fp16 of q/k/v inputs
__device__ __half g_wh[(size_t)3 * DMODEL * DMODEL];  // fp16(in_proj_weight)
__device__ __half g_woh[(size_t)DMODEL * DMODEL];     // fp16(out_w)
__device__ __half g_q[(size_t)BATCH * HEADS * NQ * DK];
__device__ __half g_k[(size_t)BATCH * HEADS * NKV_PAD * DK];
__device__ __half g_v[(size_t)BATCH * HEADS * NKV_PAD * DK];
__device__ __half g_aoh[(size_t)ROWS * DMODEL];       // attn out (row = n*B+b)

// ------------------------- helpers ------------------------------------------
__device__ __forceinline__ uint32_t s2u(const void* p) {
    uint32_t a;
    asm("{ .reg .u64 t; cvta.to.shared.u64 t, %1; cvt.u32.u64 %0, t; }"
        : "=r"(a) : "l"(p));
    return a;
}

__device__ __forceinline__ void cpasync16(uint32_t dst, const void* src) {
    asm volatile("cp.async.cg.shared.global [%0], [%1], 16;"
                 :: "r"(dst), "l"(src));
}

#define LDM_X4(r, addr) \
    asm volatile("ldmatrix.sync.aligned.m8n8.x4.shared.b16 {%0,%1,%2,%3}, [%4];" \
                 : "=r"((r)[0]), "=r"((r)[1]), "=r"((r)[2]), "=r"((r)[3]) \
                 : "r"(addr))

#define LDM_X4_T(r, addr) \
    asm volatile("ldmatrix.sync.aligned.m8n8.x4.trans.shared.b16 {%0,%1,%2,%3}, [%4];" \
                 : "=r"((r)[0]), "=r"((r)[1]), "=r"((r)[2]), "=r"((r)[3]) \
                 : "r"(addr))

__device__ __forceinline__ void mma16816(float* c, const uint32_t* a,
                                         uint32_t b0, uint32_t b1) {
    asm volatile(
        "mma.sync.aligned.m16n8k16.row.col.f32.f16.f16.f32 "
        "{%0,%1,%2,%3}, {%4,%5,%6,%7}, {%8,%9}, {%0,%1,%2,%3};"
        : "+f"(c[0]), "+f"(c[1]), "+f"(c[2]), "+f"(c[3])
        : "r"(a[0]), "r"(a[1]), "r"(a[2]), "r"(a[3]), "r"(b0), "r"(b1));
}

__device__ __forceinline__ uint32_t packh2(float x, float y) {
    __half2 h = __floats2half2_rn(x, y);
    return *(uint32_t*)&h;
}

// ------------------------- conversion prepass (hi only) ---------------------
__global__ void convert_kernel(const float* __restrict__ q, const float* __restrict__ k,
                               const float* __restrict__ v, const float* __restrict__ wi,
                               const float* __restrict__ wo) {
    size_t i = (size_t)blockIdx.x * blockDim.x + threadIdx.x;
    const size_t NIN = 2097152;   // float4 per input tensor (8192*1024/4)
    if (i < 3 * NIN) {
        int which = (int)(i / NIN);
        size_t off = (i - (size_t)which * NIN) * 4;
        const float* s = (which == 0) ? q : (which == 1) ? k : v;
        float4 f = *(const float4*)(s + off);
        __half hv[4] = {__float2half_rn(f.x), __float2half_rn(f.y),
                        __float2half_rn(f.z), __float2half_rn(f.w)};
        *(uint2*)&g_inh[(size_t)which * 8388608 + off] = *(uint2*)hv;
    } else if (i < 3 * NIN + 786432) {
        size_t off = (i - 3 * NIN) * 4;
        float4 f = *(const float4*)(wi + off);
        __half hv[4] = {__float2half_rn(f.x), __float2half_rn(f.y),
                        __float2half_rn(f.z), __float2half_rn(f.w)};
        *(uint2*)&g_wh[off] = *(uint2*)hv;
    } else if (i < 3 * NIN + 786432 + 262144) {
        size_t off = (i - 3 * NIN - 786432) * 4;
        float4 f = *(const float4*)(wo + off);
        __half hv[4] = {__float2half_rn(f.x), __float2half_rn(f.y),
                        __float2half_rn(f.z), __float2half_rn(f.w)};
        *(uint2*)&g_woh[off] = *(uint2*)hv;
    }
}

// ------------------------- memory slot / pad fill ---------------------------
__global__ void fill_mem_kernel(const float* __restrict__ m_k,
                                const float* __restrict__ m_v) {
    int idx = blockIdx.x * blockDim.x + threadIdx.x;
    if (idx >= BATCH * HEADS * 64 * DK) return;
    int d = idx & 63;
    int s = (idx >> 6) & 63;
    int h = (idx >> 12) & 15;
    int b = idx >> 16;
    size_t o = (((size_t)(b * HEADS + h)) * NKV_PAD + 1024 + s) * DK + d;
    if (s < MSLOT) {
        g_k[o] = __float2half_rn(32.0f * m_k[s * DMODEL + h * 64 + d]);
        g_v[o] = __float2half_rn(2.8284271247461903f * m_v[s * DMODEL + h * 64 + d]);
    } else {
        g_k[o] = __float2half_rn(0.0f);
        g_v[o] = __float2half_rn(0.0f);
    }
}

// ------------------------- HMMA GEMM (cp.async 4-stage, single pass) --------
static constexpr int GSTAGES = 4;
static constexpr int A_BYTES = 128 * 80;
static constexpr int STAGE_B = 2 * A_BYTES;
static constexpr int GEMM_SMEM = GSTAGES * STAGE_B;  // 81920

template <int NT, int EPI>
__global__ void __launch_bounds__(256, 2) gemm_mma(const float* __restrict__ bias,
                                                   float* __restrict__ outp) {
    extern __shared__ __align__(128) char sm[];
    const uint32_t smb = s2u(sm);
    const int tid = threadIdx.x, warp = tid >> 5, lane = tid & 31;
    const int rowbase = blockIdx.y * 128, colbase = blockIdx.x * 128;
    const int wr = (warp >> 2) * 64, wc = (warp & 3) * 32;

    const __half *ah, *bhp;
    if (EPI == 0) {
        const int z = colbase >> 10;
        ah = g_inh + (size_t)z * 8388608;
        bhp = g_wh;
    } else {
        ah = g_aoh;
        bhp = g_woh;
    }

    float acc[4][4][4];
#pragma unroll
    for (int i = 0; i < 4; i++)
#pragma unroll
        for (int j = 0; j < 4; j++)
#pragma unroll
            for (int u = 0; u < 4; u++) acc[i][j][u] = 0.0f;

    auto issue = [&](int kt) {
        const int slot = kt & 3;
        const int k0 = kt << 5;
        const __half* Ag = ah + (size_t)rowbase * 1024 + k0;
        const __half* Bg = bhp + (size_t)colbase * 1024 + k0;
        const uint32_t dstA = smb + slot * STAGE_B;
#pragma unroll
        for (int c = 0; c < 4; c++) {
            int idx = tid + c * 256;
            int isB = idx >> 9;
            int e = idx & 511;
            int r = e >> 2, j = e & 3;
            const __half* src = (isB ? Bg : Ag) + (size_t)r * 1024 + j * 8;
            uint32_t dst = dstA + isB * A_BYTES + r * 80 + j * 16;
            cpasync16(dst, src);
        }
    };

#pragma unroll
    for (int s = 0; s < GSTAGES - 1; s++) {
        issue(s);
        asm volatile("cp.async.commit_group;" ::: "memory");
    }

    for (int kt = 0; kt < NT; kt++) {
        if (kt + GSTAGES - 1 < NT) issue(kt + GSTAGES - 1);
        asm volatile("cp.async.commit_group;" ::: "memory");
        asm volatile("cp.async.wait_group 2;" ::: "memory");
        __syncthreads();

        const uint32_t aBase = smb + (kt & 3) * STAGE_B;
        const uint32_t bBase = aBase + A_BYTES;
#pragma unroll
        for (int k16 = 0; k16 < 2; k16++) {
            uint32_t a[4][4];
#pragma unroll
            for (int mt = 0; mt < 4; mt++) {
                uint32_t addr = aBase + (wr + mt * 16 + (lane & 15)) * 80u +
                                (k16 * 16 + ((lane >> 4) << 3)) * 2u;
                LDM_X4(a[mt], addr);
            }
            uint32_t b[2][4];
#pragma unroll
            for (int bt = 0; bt < 2; bt++) {
                uint32_t addr = bBase +
                                (wc + bt * 16 + (lane & 7) + ((lane >> 4) & 1) * 8) * 80u +
                                (k16 * 16 + ((lane >> 3) & 1) * 8) * 2u;
                LDM_X4(b[bt], addr);
            }
#pragma unroll
            for (int mt = 0; mt < 4; mt++)
#pragma unroll
                for (int nt = 0; nt < 4; nt++)
                    mma16816(acc[mt][nt], a[mt], b[nt >> 1][(nt & 1) * 2],
                             b[nt >> 1][(nt & 1) * 2 + 1]);
        }
        __syncthreads();
    }

    const int r0 = lane >> 2, cp = (lane & 3) * 2;
#pragma unroll
    for (int mt = 0; mt < 4; mt++) {
#pragma unroll
        for (int nt = 0; nt < 4; nt++) {
            const float* cc = acc[mt][nt];
            int gr = rowbase + wr + mt * 16 + r0;
            int gc = colbase + wc + nt * 8 + cp;
            if (EPI == 0) {
                const int z = gc >> 10;
                __half* dst = (z == 0) ? g_q : (z == 1) ? g_k : g_v;
                const int L = (z == 0) ? NQ : NKV_PAD;
                float b0 = __half2float(__float2half_rn(bias[gc]));
                float b1 = __half2float(__float2half_rn(bias[gc + 1]));
                int cz = gc & 1023;
                int hh = cz >> 6, dk = cz & 63;
#pragma unroll
                for (int rh = 0; rh < 2; rh++) {
                    int g = gr + rh * 8;
                    int n = g >> 3, bb = g & 7;
                    size_t o = (((size_t)(bb * HEADS + hh)) * L + n) * 64 + dk;
                    __half hv[2] = {__float2half_rn(cc[rh * 2] + b0),
                                    __float2half_rn(cc[rh * 2 + 1] + b1)};
                    *(uint32_t*)&dst[o] = *(uint32_t*)hv;
                }
            } else {
                float b0 = bias[gc], b1 = bias[gc + 1];
#pragma unroll
                for (int rh = 0; rh < 2; rh++) {
                    int g = gr + rh * 8;
                    float2 v = make_float2(cc[rh * 2] + b0, cc[rh * 2 + 1] + b1);
                    *(float2*)&outp[(size_t)g * 1024 + gc] = v;
                }
            }
        }
    }
}

// ------------------------- flash attention (register-resident FA2) ----------
// Block: 128 q rows, 8 warps x 16 rows. KV tiles of 64, double-buffered cp.async.
static constexpr int ATTN_SMEM = 16384 + 2 * 16384;

__global__ void __launch_bounds__(256, 2) attn_kernel(const float* __restrict__ mask) {
    extern __shared__ __align__(128) char smc[];
    const uint32_t smb = s2u(smc);
    const int tid = threadIdx.x, warp = tid >> 5, lane = tid & 31;
    const int qt = blockIdx.x, bh = blockIdx.y;
    const int q0 = qt * 128;
    const __half* qg = g_q + ((size_t)bh * NQ + q0) * DK;
    const __half* kg = g_k + (size_t)bh * NKV_PAD * DK;
    const __half* vg = g_v + (size_t)bh * NKV_PAD * DK;

    // ---- stage Q (swizzled 16B chunks), then per-warp a-frags scaled 1/8 ----
#pragma unroll
    for (int it = 0; it < 4; it++) {
        int idx = tid + it * 256;           // 1024 chunks
        int r = idx >> 3, c = idx & 7;
        *(uint4*)(smc + r * 128 + ((c ^ (r & 7)) * 16)) =
            *(const uint4*)(qg + (size_t)r * 64 + c * 8);
    }
    __syncthreads();

    uint32_t qa[4][4];
    {
        const __half2 sc8 = __floats2half2_rn(0.125f, 0.125f);
        int r = warp * 16 + (lane & 7) + ((lane >> 3) & 1) * 8;   // A pattern
#pragma unroll
        for (int u = 0; u < 4; u++) {
            int c = u * 2 + (lane >> 4);
            uint32_t addr = smb + r * 128 + ((c ^ (r & 7)) * 16);
            LDM_X4(qa[u], addr);
#pragma unroll
            for (int j = 0; j < 4; j++) {
                __half2 h = __hmul2(*(__half2*)&qa[u][j], sc8);
                qa[u][j] = *(uint32_t*)&h;
            }
        }
    }
    __syncthreads();   // Qs region dead; KV buffers live at +16384

    auto issueKV = [&](int t) {
        const uint32_t base = smb + 16384 + (t & 1) * 16384;
        const __half* kp = kg + (size_t)t * 64 * 64;
        const __half* vp = vg + (size_t)t * 64 * 64;
#pragma unroll
        for (int it = 0; it < 2; it++) {
            int idx = tid + it * 256;       // 512 chunks each
            int r = idx >> 3, c = idx & 7;
            uint32_t so = r * 128 + ((c ^ (r & 7)) * 16);
            cpasync16(base + so, kp + (size_t)r * 64 + c * 8);
            cpasync16(base + 8192 + so, vp + (size_t)r * 64 + c * 8);
        }
    };

    float o[8][4];
#pragma unroll
    for (int n = 0; n < 8; n++)
#pragma unroll
        for (int j = 0; j < 4; j++) o[n][j] = 0.0f;
    float mprevA = -1e30f, mprevB = -1e30f, laccA = 0.0f, laccB = 0.0f;

    const int rA = lane >> 2;
    const float* mrowA = mask + ((size_t)bh * NQ + q0 + warp * 16 + rA) * NQ +
                         2 * (lane & 3);
    const float* mrowB = mrowA + 8 * NQ;

    issueKV(0);
    asm volatile("cp.async.commit_group;" ::: "memory");

    for (int t = 0; t < 17; t++) {
        if (t < 16) {
            issueKV(t + 1);
            asm volatile("cp.async.commit_group;" ::: "memory");
            asm volatile("cp.async.wait_group 1;" ::: "memory");
        } else {
            asm volatile("cp.async.wait_group 0;" ::: "memory");
        }
        __syncthreads();

        const uint32_t kb = smb + 16384 + (t & 1) * 16384;
        const uint32_t vb = kb + 8192;

        // ---- S = (Q/8) @ K^T  (K loaded with B-operand lane pattern) ----
        float s[8][4];
#pragma unroll
        for (int n = 0; n < 8; n++)
#pragma unroll
            for (int j = 0; j < 4; j++) s[n][j] = 0.0f;
        {
            const int rn = (lane & 7) + ((lane >> 4) & 1) * 8;  // n-row offset
            const int ck = (lane >> 3) & 1;                     // k-chunk offset
#pragma unroll
            for (int g = 0; g < 4; g++) {
                int r = g * 16 + rn;
#pragma unroll
                for (int u = 0; u < 4; u++) {
                    int c = u * 2 + ck;
                    uint32_t kb4[4];
                    LDM_X4(kb4, kb + r * 128 + ((c ^ (r & 7)) * 16));
                    mma16816(s[2 * g],     qa[u], kb4[0], kb4[1]);
                    mma16816(s[2 * g + 1], qa[u], kb4[2], kb4[3]);
                }
            }
        }

        // ---- mask ----
        if (t < 16) {
            const float* mA = mrowA + t * 64;
            const float* mB = mrowB + t * 64;
#pragma unroll
            for (int n = 0; n < 8; n++) {
                float2 xa = *(const float2*)(mA + n * 8);
                float2 xb = *(const float2*)(mB + n * 8);
                s[n][0] += xa.x; s[n][1] += xa.y;
                s[n][2] += xb.x; s[n][3] += xb.y;
            }
        } else {
            // keys 1024-1031 (n==0) are memory slots (mask 0); rest padding
#pragma unroll
            for (int n = 1; n < 8; n++) {
                s[n][0] = s[n][1] = s[n][2] = s[n][3] = -1e30f;
            }
        }

        // ---- online softmax (register) ----
        float mxA = -1e30f, mxB = -1e30f;
#pragma unroll
        for (int n = 0; n < 8; n++) {
            mxA = fmaxf(mxA, fmaxf(s[n][0], s[n][1]));
            mxB = fmaxf(mxB, fmaxf(s[n][2], s[n][3]));
        }
        mxA = fmaxf(mxA, __shfl_xor_sync(0xffffffffu, mxA, 1));
        mxA = fmaxf(mxA, __shfl_xor_sync(0xffffffffu, mxA, 2));
        mxB = fmaxf(mxB, __shfl_xor_sync(0xffffffffu, mxB, 1));
        mxB = fmaxf(mxB, __shfl_xor_sync(0xffffffffu, mxB, 2));
        float mnA = fmaxf(mprevA, mxA), mnB = fmaxf(mprevB, mxB);
        float aA = __expf(mprevA - mnA), aB = __expf(mprevB - mnB);
        mprevA = mnA; mprevB = mnB;

        uint32_t pf[4][4];
        float sumA = 0.0f, sumB = 0.0f;
#pragma unroll
        for (int n = 0; n < 8; n++) {
            float p0 = __expf(s[n][0] - mnA);
            float p1 = __expf(s[n][1] - mnA);
            float p2 = __expf(s[n][2] - mnB);
            float p3 = __expf(s[n][3] - mnB);
            sumA += p0 + p1; sumB += p2 + p3;
            pf[n >> 1][(n & 1) * 2]     = packh2(p0, p1);
            pf[n >> 1][(n & 1) * 2 + 1] = packh2(p2, p3);
        }
        sumA += __shfl_xor_sync(0xffffffffu, sumA, 1);
        sumA += __shfl_xor_sync(0xffffffffu, sumA, 2);
        sumB += __shfl_xor_sync(0xffffffffu, sumB, 1);
        sumB += __shfl_xor_sync(0xffffffffu, sumB, 2);
        laccA = laccA * aA + sumA;
        laccB = laccB * aB + sumB;
#pragma unroll
        for (int n = 0; n < 8; n++) {
            o[n][0] *= aA; o[n][1] *= aA;
            o[n][2] *= aB; o[n][3] *= aB;
        }

        // ---- O += P @ V (V trans-loaded) ----
        {
            int rr = (lane & 7) + ((lane >> 3) & 1) * 8;
#pragma unroll
            for (int u = 0; u < 4; u++) {
                int r = u * 16 + rr;
#pragma unroll
                for (int dp = 0; dp < 4; dp++) {
                    int c = dp * 2 + (lane >> 4);
                    uint32_t vb4[4];
                    LDM_X4_T(vb4, vb + r * 128 + ((c ^ (r & 7)) * 16));
                    mma16816(o[2 * dp],     pf[u], vb4[0], vb4[1]);
                    mma16816(o[2 * dp + 1], pf[u], vb4[2], vb4[3]);
                }
            }
        }
        __syncthreads();
    }

    // ---- finalize: O /= l, write fp16 to g_aoh (row = q*B + b) ----
    const int b = bh >> 4, h = bh & 15;
    const int qrA = q0 + warp * 16 + rA;
    const float invA = 1.0f / laccA, invB = 1.0f / laccB;
#pragma unroll
    for (int n = 0; n < 8; n++) {
        int dk = h * 64 + n * 8 + 2 * (lane & 3);
        {
            __half hv[2] = {__float2half_rn(o[n][0] * invA),
                            __float2half_rn(o[n][1] * invA)};
            *(uint32_t*)&g_aoh[((size_t)qrA * BATCH + b) * DMODEL + dk] =
                *(uint32_t*)hv;
        }
        {
            __half hv[2] = {__float2half_rn(o[n][2] * invB),
                            __float2half_rn(o[n][3] * invB)};
            *(uint32_t*)&g_aoh[((size_t)(qrA + 8) * BATCH + b) * DMODEL + dk] =
                *(uint32_t*)hv;
        }
    }
}

// ------------------------- launch -------------------------------------------
extern "C" void kernel_launch(void* const* d_in, const int* in_sizes, int n_in,
                              void* d_out, int out_size) {
    const float* queries = (const float*)d_in[0];
    const float* keys    = (const float*)d_in[1];
    const float* values  = (const float*)d_in[2];
    const float* m_k     = (const float*)d_in[3];
    const float* m_v     = (const float*)d_in[4];
    const float* mask    = (const float*)d_in[5];
    const float* in_w    = (const float*)d_in[6];
    const float* in_b    = (const float*)d_in[7];
    const float* out_w   = (const float*)d_in[8];
    const float* out_b   = (const float*)d_in[9];
    float* out = (float*)d_out;
    (void)in_sizes; (void)n_in; (void)out_size;

    cudaFuncSetAttribute(attn_kernel, cudaFuncAttributeMaxDynamicSharedMemorySize,
                         ATTN_SMEM);
    cudaFuncSetAttribute(gemm_mma<32, 0>, cudaFuncAttributeMaxDynamicSharedMemorySize,
                         GEMM_SMEM);
    cudaFuncSetAttribute(gemm_mma<32, 1>, cudaFuncAttributeMaxDynamicSharedMemorySize,
                         GEMM_SMEM);

    convert_kernel<<<28672, 256>>>(queries, keys, values, in_w, out_w);
    fill_mem_kernel<<<2048, 256>>>(m_k, m_v);
    gemm_mma<32, 0><<<dim3(24, 64), 256, GEMM_SMEM>>>(in_b, nullptr);  // QKV proj
    attn_kernel<<<dim3(8, 128), 256, ATTN_SMEM>>>(mask);
    gemm_mma<32, 1><<<dim3(8, 64), 256, GEMM_SMEM>>>(out_b, out);      // out proj
}

// round 7
// speedup vs baseline: 2.5444x; 1.1007x over previous
#include <cuda_runtime.h>
#include <cuda_fp16.h>
#include <math.h>
#include <stdint.h>

#define HEADS   16
#define DK      64
#define DMODEL  1024
#define NQ      1024
#define BATCH   8
#define MSLOT   8
#define NKV     1032
#define NKV_PAD 1088
#define ROWS    (NQ * BATCH)

// ------------------------- device scratch (no allocs allowed) ---------------
__device__ __half g_inh[(size_t)3 * ROWS * DMODEL];   // fp16 of q/k/v inputs
__device__ __half g_wh[(size_t)3 * DMODEL * DMODEL];  // fp16(in_proj_weight)
__device__ __half g_woh[(size_t)DMODEL * DMODEL];     // fp16(out_w)
__device__ __half g_q[(size_t)BATCH * HEADS * NQ * DK];
__device__ __half g_k[(size_t)BATCH * HEADS * NKV_PAD * DK];
__device__ __half g_v[(size_t)BATCH * HEADS * NKV_PAD * DK];
__device__ __half g_aoh[(size_t)ROWS * DMODEL];       // attn out (row = n*B+b)

// ------------------------- helpers ------------------------------------------
__device__ __forceinline__ uint32_t s2u(const void* p) {
    uint32_t a;
    asm("{ .reg .u64 t; cvta.to.shared.u64 t, %1; cvt.u32.u64 %0, t; }"
        : "=r"(a) : "l"(p));
    return a;
}

__device__ __forceinline__ void cpasync16(uint32_t dst, const void* src) {
    asm volatile("cp.async.cg.shared.global [%0], [%1], 16;"
                 :: "r"(dst), "l"(src));
}

#define LDM_X4(r, addr) \
    asm volatile("ldmatrix.sync.aligned.m8n8.x4.shared.b16 {%0,%1,%2,%3}, [%4];" \
                 : "=r"((r)[0]), "=r"((r)[1]), "=r"((r)[2]), "=r"((r)[3]) \
                 : "r"(addr))

#define LDM_X4_T(r, addr) \
    asm volatile("ldmatrix.sync.aligned.m8n8.x4.trans.shared.b16 {%0,%1,%2,%3}, [%4];" \
                 : "=r"((r)[0]), "=r"((r)[1]), "=r"((r)[2]), "=r"((r)[3]) \
                 : "r"(addr))

__device__ __forceinline__ void mma16816(float* c, const uint32_t* a,
                                         uint32_t b0, uint32_t b1) {
    asm volatile(
        "mma.sync.aligned.m16n8k16.row.col.f32.f16.f16.f32 "
        "{%0,%1,%2,%3}, {%4,%5,%6,%7}, {%8,%9}, {%0,%1,%2,%3};"
        : "+f"(c[0]), "+f"(c[1]), "+f"(c[2]), "+f"(c[3])
        : "r"(a[0]), "r"(a[1]), "r"(a[2]), "r"(a[3]), "r"(b0), "r"(b1));
}

__device__ __forceinline__ uint32_t packh2(float x, float y) {
    __half2 h = __floats2half2_rn(x, y);
    return *(uint32_t*)&h;
}

// ------------------------- conversion prepass (hi only) ---------------------
__global__ void convert_kernel(const float* __restrict__ q, const float* __restrict__ k,
                               const float* __restrict__ v, const float* __restrict__ wi,
                               const float* __restrict__ wo) {
    size_t i = (size_t)blockIdx.x * blockDim.x + threadIdx.x;
    const size_t NIN = 2097152;   // float4 per input tensor (8192*1024/4)
    if (i < 3 * NIN) {
        int which = (int)(i / NIN);
        size_t off = (i - (size_t)which * NIN) * 4;
        const float* s = (which == 0) ? q : (which == 1) ? k : v;
        float4 f = *(const float4*)(s + off);
        __half hv[4] = {__float2half_rn(f.x), __float2half_rn(f.y),
                        __float2half_rn(f.z), __float2half_rn(f.w)};
        *(uint2*)&g_inh[(size_t)which * 8388608 + off] = *(uint2*)hv;
    } else if (i < 3 * NIN + 786432) {
        size_t off = (i - 3 * NIN) * 4;
        float4 f = *(const float4*)(wi + off);
        __half hv[4] = {__float2half_rn(f.x), __float2half_rn(f.y),
                        __float2half_rn(f.z), __float2half_rn(f.w)};
        *(uint2*)&g_wh[off] = *(uint2*)hv;
    } else if (i < 3 * NIN + 786432 + 262144) {
        size_t off = (i - 3 * NIN - 786432) * 4;
        float4 f = *(const float4*)(wo + off);
        __half hv[4] = {__float2half_rn(f.x), __float2half_rn(f.y),
                        __float2half_rn(f.z), __float2half_rn(f.w)};
        *(uint2*)&g_woh[off] = *(uint2*)hv;
    }
}

// ------------------------- memory slot / pad fill ---------------------------
__global__ void fill_mem_kernel(const float* __restrict__ m_k,
                                const float* __restrict__ m_v) {
    int idx = blockIdx.x * blockDim.x + threadIdx.x;
    if (idx >= BATCH * HEADS * 64 * DK) return;
    int d = idx & 63;
    int s = (idx >> 6) & 63;
    int h = (idx >> 12) & 15;
    int b = idx >> 16;
    size_t o = (((size_t)(b * HEADS + h)) * NKV_PAD + 1024 + s) * DK + d;
    if (s < MSLOT) {
        g_k[o] = __float2half_rn(32.0f * m_k[s * DMODEL + h * 64 + d]);
        g_v[o] = __float2half_rn(2.8284271247461903f * m_v[s * DMODEL + h * 64 + d]);
    } else {
        g_k[o] = __float2half_rn(0.0f);
        g_v[o] = __float2half_rn(0.0f);
    }
}

// ------------------------- HMMA GEMM (cp.async 4-stage, band-swizzled) ------
static constexpr int GSTAGES = 4;
static constexpr int A_BYTES = 128 * 80;
static constexpr int STAGE_B = 2 * A_BYTES;
static constexpr int GEMM_SMEM = GSTAGES * STAGE_B;  // 81920

template <int NT, int EPI>
__global__ void __launch_bounds__(256, 2) gemm_mma(const float* __restrict__ bias,
                                                   float* __restrict__ outp) {
    extern __shared__ __align__(128) char sm[];
    const uint32_t smb = s2u(sm);
    const int tid = threadIdx.x, warp = tid >> 5, lane = tid & 31;

    // band rasterization: consecutive launch ids cover 8 row-tiles x sweeping
    // col-tiles, so a wave's A/B working set stays L2-resident.
    const int lin = blockIdx.y * gridDim.x + blockIdx.x;
    const int bandsz = gridDim.x * 8;
    const int band = lin / bandsz, rem = lin % bandsz;
    const int by = band * 8 + (rem & 7);
    const int bx = rem >> 3;
    const int rowbase = by * 128, colbase = bx * 128;
    const int wr = (warp >> 2) * 64, wc = (warp & 3) * 32;

    const __half *ah, *bhp;
    if (EPI == 0) {
        const int z = colbase >> 10;
        ah = g_inh + (size_t)z * 8388608;
        bhp = g_wh;
    } else {
        ah = g_aoh;
        bhp = g_woh;
    }

    float acc[4][4][4];
#pragma unroll
    for (int i = 0; i < 4; i++)
#pragma unroll
        for (int j = 0; j < 4; j++)
#pragma unroll
            for (int u = 0; u < 4; u++) acc[i][j][u] = 0.0f;

    auto issue = [&](int kt) {
        const int slot = kt & 3;
        const int k0 = kt << 5;
        const __half* Ag = ah + (size_t)rowbase * 1024 + k0;
        const __half* Bg = bhp + (size_t)colbase * 1024 + k0;
        const uint32_t dstA = smb + slot * STAGE_B;
#pragma unroll
        for (int c = 0; c < 4; c++) {
            int idx = tid + c * 256;
            int isB = idx >> 9;
            int e = idx & 511;
            int r = e >> 2, j = e & 3;
            const __half* src = (isB ? Bg : Ag) + (size_t)r * 1024 + j * 8;
            uint32_t dst = dstA + isB * A_BYTES + r * 80 + j * 16;
            cpasync16(dst, src);
        }
    };

#pragma unroll
    for (int s = 0; s < GSTAGES - 1; s++) {
        issue(s);
        asm volatile("cp.async.commit_group;" ::: "memory");
    }

    for (int kt = 0; kt < NT; kt++) {
        if (kt + GSTAGES - 1 < NT) issue(kt + GSTAGES - 1);
        asm volatile("cp.async.commit_group;" ::: "memory");
        asm volatile("cp.async.wait_group 2;" ::: "memory");
        __syncthreads();

        const uint32_t aBase = smb + (kt & 3) * STAGE_B;
        const uint32_t bBase = aBase + A_BYTES;
#pragma unroll
        for (int k16 = 0; k16 < 2; k16++) {
            uint32_t a[4][4];
#pragma unroll
            for (int mt = 0; mt < 4; mt++) {
                uint32_t addr = aBase + (wr + mt * 16 + (lane & 15)) * 80u +
                                (k16 * 16 + ((lane >> 4) << 3)) * 2u;
                LDM_X4(a[mt], addr);
            }
            uint32_t b[2][4];
#pragma unroll
            for (int bt = 0; bt < 2; bt++) {
                uint32_t addr = bBase +
                                (wc + bt * 16 + (lane & 7) + ((lane >> 4) & 1) * 8) * 80u +
                                (k16 * 16 + ((lane >> 3) & 1) * 8) * 2u;
                LDM_X4(b[bt], addr);
            }
#pragma unroll
            for (int mt = 0; mt < 4; mt++)
#pragma unroll
                for (int nt = 0; nt < 4; nt++)
                    mma16816(acc[mt][nt], a[mt], b[nt >> 1][(nt & 1) * 2],
                             b[nt >> 1][(nt & 1) * 2 + 1]);
        }
        __syncthreads();
    }

    const int r0 = lane >> 2, cp = (lane & 3) * 2;
#pragma unroll
    for (int mt = 0; mt < 4; mt++) {
#pragma unroll
        for (int nt = 0; nt < 4; nt++) {
            const float* cc = acc[mt][nt];
            int gr = rowbase + wr + mt * 16 + r0;
            int gc = colbase + wc + nt * 8 + cp;
            if (EPI == 0) {
                const int z = gc >> 10;
                __half* dst = (z == 0) ? g_q : (z == 1) ? g_k : g_v;
                const int L = (z == 0) ? NQ : NKV_PAD;
                float b0 = __half2float(__float2half_rn(bias[gc]));
                float b1 = __half2float(__float2half_rn(bias[gc + 1]));
                int cz = gc & 1023;
                int hh = cz >> 6, dk = cz & 63;
#pragma unroll
                for (int rh = 0; rh < 2; rh++) {
                    int g = gr + rh * 8;
                    int n = g >> 3, bb = g & 7;
                    size_t o = (((size_t)(bb * HEADS + hh)) * L + n) * 64 + dk;
                    __half hv[2] = {__float2half_rn(cc[rh * 2] + b0),
                                    __float2half_rn(cc[rh * 2 + 1] + b1)};
                    *(uint32_t*)&dst[o] = *(uint32_t*)hv;
                }
            } else {
                float b0 = bias[gc], b1 = bias[gc + 1];
#pragma unroll
                for (int rh = 0; rh < 2; rh++) {
                    int g = gr + rh * 8;
                    float2 v = make_float2(cc[rh * 2] + b0, cc[rh * 2 + 1] + b1);
                    *(float2*)&outp[(size_t)g * 1024 + gc] = v;
                }
            }
        }
    }
}

// ------------------------- flash attention (reg FA2, 3-stage, 1 sync) -------
// Block: 128 q rows, 8 warps x 16 rows. KV tiles of 64, 3-buffer cp.async ring.
static constexpr int ATTN_SMEM = 16384 + 3 * 16384;   // Q + 3 KV stages

__global__ void __launch_bounds__(256, 2) attn_kernel(const float* __restrict__ mask) {
    extern __shared__ __align__(128) char smc[];
    const uint32_t smb = s2u(smc);
    const int tid = threadIdx.x, warp = tid >> 5, lane = tid & 31;
    const int qt = blockIdx.x, bh = blockIdx.y;
    const int q0 = qt * 128;
    const __half* qg = g_q + ((size_t)bh * NQ + q0) * DK;
    const __half* kg = g_k + (size_t)bh * NKV_PAD * DK;
    const __half* vg = g_v + (size_t)bh * NKV_PAD * DK;

    auto issueKV = [&](int t) {
        const uint32_t base = smb + 16384 + (t % 3) * 16384;
        const __half* kp = kg + (size_t)t * 64 * 64;
        const __half* vp = vg + (size_t)t * 64 * 64;
#pragma unroll
        for (int it = 0; it < 2; it++) {
            int idx = tid + it * 256;       // 512 chunks each
            int r = idx >> 3, c = idx & 7;
            uint32_t so = r * 128 + ((c ^ (r & 7)) * 16);
            cpasync16(base + so, kp + (size_t)r * 64 + c * 8);
            cpasync16(base + 8192 + so, vp + (size_t)r * 64 + c * 8);
        }
    };

    // prologue: start KV(0), KV(1) before Q staging so they overlap
    issueKV(0);
    asm volatile("cp.async.commit_group;" ::: "memory");
    issueKV(1);
    asm volatile("cp.async.commit_group;" ::: "memory");

    // ---- stage Q (swizzled 16B chunks), then per-warp a-frags scaled 1/8 ----
#pragma unroll
    for (int it = 0; it < 4; it++) {
        int idx = tid + it * 256;           // 1024 chunks
        int r = idx >> 3, c = idx & 7;
        *(uint4*)(smc + r * 128 + ((c ^ (r & 7)) * 16)) =
            *(const uint4*)(qg + (size_t)r * 64 + c * 8);
    }
    __syncthreads();

    uint32_t qa[4][4];
    {
        const __half2 sc8 = __floats2half2_rn(0.125f, 0.125f);
        int r = warp * 16 + (lane & 7) + ((lane >> 3) & 1) * 8;   // A pattern
#pragma unroll
        for (int u = 0; u < 4; u++) {
            int c = u * 2 + (lane >> 4);
            uint32_t addr = smb + r * 128 + ((c ^ (r & 7)) * 16);
            LDM_X4(qa[u], addr);
#pragma unroll
            for (int j = 0; j < 4; j++) {
                __half2 h = __hmul2(*(__half2*)&qa[u][j], sc8);
                qa[u][j] = *(uint32_t*)&h;
            }
        }
    }

    float o[8][4];
#pragma unroll
    for (int n = 0; n < 8; n++)
#pragma unroll
        for (int j = 0; j < 4; j++) o[n][j] = 0.0f;
    float mprevA = -1e30f, mprevB = -1e30f, laccA = 0.0f, laccB = 0.0f;

    const int rA = lane >> 2;
    const float* mrowA = mask + ((size_t)bh * NQ + q0 + warp * 16 + rA) * NQ +
                         2 * (lane & 3);
    const float* mrowB = mrowA + 8 * NQ;

    for (int t = 0; t < 17; t++) {
        asm volatile("cp.async.wait_group 1;" ::: "memory");
        __syncthreads();

        const uint32_t kb = smb + 16384 + (t % 3) * 16384;
        const uint32_t vb = kb + 8192;

        // ---- init S with the additive mask (hides mask DRAM latency) ----
        float s[8][4];
        if (t < 16) {
            const float* mA = mrowA + t * 64;
            const float* mB = mrowB + t * 64;
#pragma unroll
            for (int n = 0; n < 8; n++) {
                float2 xa = *(const float2*)(mA + n * 8);
                float2 xb = *(const float2*)(mB + n * 8);
                s[n][0] = xa.x; s[n][1] = xa.y;
                s[n][2] = xb.x; s[n][3] = xb.y;
            }
        } else {
            // keys 1024-1031 (n==0) are memory slots (mask 0); rest padding
            s[0][0] = s[0][1] = s[0][2] = s[0][3] = 0.0f;
#pragma unroll
            for (int n = 1; n < 8; n++)
                s[n][0] = s[n][1] = s[n][2] = s[n][3] = -1e30f;
        }

        // ---- S += (Q/8) @ K^T  (K loaded with B-operand lane pattern) ----
        {
            const int rn = (lane & 7) + ((lane >> 4) & 1) * 8;  // n-row offset
            const int ck = (lane >> 3) & 1;                     // k-chunk offset
#pragma unroll
            for (int g = 0; g < 4; g++) {
                int r = g * 16 + rn;
#pragma unroll
                for (int u = 0; u < 4; u++) {
                    int c = u * 2 + ck;
                    uint32_t kb4[4];
                    LDM_X4(kb4, kb + r * 128 + ((c ^ (r & 7)) * 16));
                    mma16816(s[2 * g],     qa[u], kb4[0], kb4[1]);
                    mma16816(s[2 * g + 1], qa[u], kb4[2], kb4[3]);
                }
            }
        }

        // ---- online softmax (register) ----
        float mxA = -1e30f, mxB = -1e30f;
#pragma unroll
        for (int n = 0; n < 8; n++) {
            mxA = fmaxf(mxA, fmaxf(s[n][0], s[n][1]));
            mxB = fmaxf(mxB, fmaxf(s[n][2], s[n][3]));
        }
        mxA = fmaxf(mxA, __shfl_xor_sync(0xffffffffu, mxA, 1));
        mxA = fmaxf(mxA, __shfl_xor_sync(0xffffffffu, mxA, 2));
        mxB = fmaxf(mxB, __shfl_xor_sync(0xffffffffu, mxB, 1));
        mxB = fmaxf(mxB, __shfl_xor_sync(0xffffffffu, mxB, 2));
        float mnA = fmaxf(mprevA, mxA), mnB = fmaxf(mprevB, mxB);
        float aA = __expf(mprevA - mnA), aB = __expf(mprevB - mnB);
        mprevA = mnA; mprevB = mnB;

        uint32_t pf[4][4];
        float sumA = 0.0f, sumB = 0.0f;
#pragma unroll
        for (int n = 0; n < 8; n++) {
            float p0 = __expf(s[n][0] - mnA);
            float p1 = __expf(s[n][1] - mnA);
            float p2 = __expf(s[n][2] - mnB);
            float p3 = __expf(s[n][3] - mnB);
            sumA += p0 + p1; sumB += p2 + p3;
            pf[n >> 1][(n & 1) * 2]     = packh2(p0, p1);
            pf[n >> 1][(n & 1) * 2 + 1] = packh2(p2, p3);
        }
        sumA += __shfl_xor_sync(0xffffffffu, sumA, 1);
        sumA += __shfl_xor_sync(0xffffffffu, sumA, 2);
        sumB += __shfl_xor_sync(0xffffffffu, sumB, 1);
        sumB += __shfl_xor_sync(0xffffffffu, sumB, 2);
        laccA = laccA * aA + sumA;
        laccB = laccB * aB + sumB;
#pragma unroll
        for (int n = 0; n < 8; n++) {
            o[n][0] *= aA; o[n][1] *= aA;
            o[n][2] *= aB; o[n][3] *= aB;
        }

        // ---- O += P @ V (V trans-loaded) ----
        {
            int rr = (lane & 7) + ((lane >> 3) & 1) * 8;
#pragma unroll
            for (int u = 0; u < 4; u++) {
                int r = u * 16 + rr;
#pragma unroll
                for (int dp = 0; dp < 4; dp++) {
                    int c = dp * 2 + (lane >> 4);
                    uint32_t vb4[4];
                    LDM_X4_T(vb4, vb + r * 128 + ((c ^ (r & 7)) * 16));
                    mma16816(o[2 * dp],     pf[u], vb4[0], vb4[1]);
                    mma16816(o[2 * dp + 1], pf[u], vb4[2], vb4[3]);
                }
            }
        }

        // issue t+2 into ring slot (t+2)%3; safe: its last readers were iter
        // t-1, and every warp passed this iteration's top sync already.
        if (t + 2 < 17) issueKV(t + 2);
        asm volatile("cp.async.commit_group;" ::: "memory");
    }

    // ---- finalize: O /= l, write fp16 to g_aoh (row = q*B + b) ----
    const int b = bh >> 4, h = bh & 15;
    const int qrA = q0 + warp * 16 + rA;
    const float invA = 1.0f / laccA, invB = 1.0f / laccB;
#pragma unroll
    for (int n = 0; n < 8; n++) {
        int dk = h * 64 + n * 8 + 2 * (lane & 3);
        {
            __half hv[2] = {__float2half_rn(o[n][0] * invA),
                            __float2half_rn(o[n][1] * invA)};
            *(uint32_t*)&g_aoh[((size_t)qrA * BATCH + b) * DMODEL + dk] =
                *(uint32_t*)hv;
        }
        {
            __half hv[2] = {__float2half_rn(o[n][2] * invB),
                            __float2half_rn(o[n][3] * invB)};
            *(uint32_t*)&g_aoh[((size_t)(qrA + 8) * BATCH + b) * DMODEL + dk] =
                *(uint32_t*)hv;
        }
    }
}

// ------------------------- launch -------------------------------------------
extern "C" void kernel_launch(void* const* d_in, const int* in_sizes, int n_in,
                              void* d_out, int out_size) {
    const float* queries = (const float*)d_in[0];
    const float* keys    = (const float*)d_in[1];
    const float* values  = (const float*)d_in[2];
    const float* m_k     = (const float*)d_in[3];
    const float* m_v     = (const float*)d_in[4];
    const float* mask    = (const float*)d_in[5];
    const float* in_w    = (const float*)d_in[6];
    const float* in_b    = (const float*)d_in[7];
    const float* out_w   = (const float*)d_in[8];
    const float* out_b   = (const float*)d_in[9];
    float* out = (float*)d_out;
    (void)in_sizes; (void)n_in; (void)out_size;

    cudaFuncSetAttribute(attn_kernel, cudaFuncAttributeMaxDynamicSharedMemorySize,
                         ATTN_SMEM);
    cudaFuncSetAttribute(gemm_mma<32, 0>, cudaFuncAttributeMaxDynamicSharedMemorySize,
                         GEMM_SMEM);
    cudaFuncSetAttribute(gemm_mma<32, 1>, cudaFuncAttributeMaxDynamicSharedMemorySize,
                         GEMM_SMEM);

    convert_kernel<<<28672, 256>>>(queries, keys, values, in_w, out_w);
    fill_mem_kernel<<<2048, 256>>>(m_k, m_v);
    gemm_mma<32, 0><<<dim3(24, 64), 256, GEMM_SMEM>>>(in_b, nullptr);  // QKV proj
    attn_kernel<<<dim3(8, 128), 256, ATTN_SMEM>>>(mask);
    gemm_mma<32, 1><<<dim3(8, 64), 256, GEMM_SMEM>>>(out_b, out);      // out proj
}

// round 8
// speedup vs baseline: 3.0063x; 1.1815x over previous
#include <cuda_runtime.h>
#include <cuda_fp16.h>
#include <math.h>
#include <stdint.h>

#define HEADS   16
#define DK      64
#define DMODEL  1024
#define NQ      1024
#define BATCH   8
#define MSLOT   8
#define NKV     1032
#define NKV_PAD 1088
#define ROWS    (NQ * BATCH)

// ------------------------- device scratch (no allocs allowed) ---------------
__device__ __half g_inh[(size_t)3 * ROWS * DMODEL];   // fp16 of q/k/v inputs
__device__ __half g_wh[(size_t)3 * DMODEL * DMODEL];  // fp16(in_proj_weight)
__device__ __half g_woh[(size_t)DMODEL * DMODEL];     // fp16(out_w)
__device__ __half g_q[(size_t)BATCH * HEADS * NQ * DK];
__device__ __half g_k[(size_t)BATCH * HEADS * NKV_PAD * DK];
__device__ __half g_v[(size_t)BATCH * HEADS * NKV_PAD * DK];
__device__ __half g_aoh[(size_t)ROWS * DMODEL];       // attn out (row = n*B+b)

// ------------------------- helpers ------------------------------------------
__device__ __forceinline__ uint32_t s2u(const void* p) {
    uint32_t a;
    asm("{ .reg .u64 t; cvta.to.shared.u64 t, %1; cvt.u32.u64 %0, t; }"
        : "=r"(a) : "l"(p));
    return a;
}

__device__ __forceinline__ void cpasync16(uint32_t dst, const void* src) {
    asm volatile("cp.async.cg.shared.global [%0], [%1], 16;"
                 :: "r"(dst), "l"(src));
}

#define LDM_X4(r, addr) \
    asm volatile("ldmatrix.sync.aligned.m8n8.x4.shared.b16 {%0,%1,%2,%3}, [%4];" \
                 : "=r"((r)[0]), "=r"((r)[1]), "=r"((r)[2]), "=r"((r)[3]) \
                 : "r"(addr))

#define LDM_X4_T(r, addr) \
    asm volatile("ldmatrix.sync.aligned.m8n8.x4.trans.shared.b16 {%0,%1,%2,%3}, [%4];" \
                 : "=r"((r)[0]), "=r"((r)[1]), "=r"((r)[2]), "=r"((r)[3]) \
                 : "r"(addr))

__device__ __forceinline__ void mma16816(float* c, const uint32_t* a,
                                         uint32_t b0, uint32_t b1) {
    asm volatile(
        "mma.sync.aligned.m16n8k16.row.col.f32.f16.f16.f32 "
        "{%0,%1,%2,%3}, {%4,%5,%6,%7}, {%8,%9}, {%0,%1,%2,%3};"
        : "+f"(c[0]), "+f"(c[1]), "+f"(c[2]), "+f"(c[3])
        : "r"(a[0]), "r"(a[1]), "r"(a[2]), "r"(a[3]), "r"(b0), "r"(b1));
}

__device__ __forceinline__ uint32_t packh2(float x, float y) {
    __half2 h = __floats2half2_rn(x, y);
    return *(uint32_t*)&h;
}

// ------------------------- conversion prepass (hi only) ---------------------
__global__ void convert_kernel(const float* __restrict__ q, const float* __restrict__ k,
                               const float* __restrict__ v, const float* __restrict__ wi,
                               const float* __restrict__ wo) {
    size_t i = (size_t)blockIdx.x * blockDim.x + threadIdx.x;
    const size_t NIN = 2097152;   // float4 per input tensor (8192*1024/4)
    if (i < 3 * NIN) {
        int which = (int)(i / NIN);
        size_t off = (i - (size_t)which * NIN) * 4;
        const float* s = (which == 0) ? q : (which == 1) ? k : v;
        float4 f = *(const float4*)(s + off);
        __half hv[4] = {__float2half_rn(f.x), __float2half_rn(f.y),
                        __float2half_rn(f.z), __float2half_rn(f.w)};
        *(uint2*)&g_inh[(size_t)which * 8388608 + off] = *(uint2*)hv;
    } else if (i < 3 * NIN + 786432) {
        size_t off = (i - 3 * NIN) * 4;
        float4 f = *(const float4*)(wi + off);
        __half hv[4] = {__float2half_rn(f.x), __float2half_rn(f.y),
                        __float2half_rn(f.z), __float2half_rn(f.w)};
        *(uint2*)&g_wh[off] = *(uint2*)hv;
    } else if (i < 3 * NIN + 786432 + 262144) {
        size_t off = (i - 3 * NIN - 786432) * 4;
        float4 f = *(const float4*)(wo + off);
        __half hv[4] = {__float2half_rn(f.x), __float2half_rn(f.y),
                        __float2half_rn(f.z), __float2half_rn(f.w)};
        *(uint2*)&g_woh[off] = *(uint2*)hv;
    }
}

// ------------------------- memory slot / pad fill ---------------------------
__global__ void fill_mem_kernel(const float* __restrict__ m_k,
                                const float* __restrict__ m_v) {
    int idx = blockIdx.x * blockDim.x + threadIdx.x;
    if (idx >= BATCH * HEADS * 64 * DK) return;
    int d = idx & 63;
    int s = (idx >> 6) & 63;
    int h = (idx >> 12) & 15;
    int b = idx >> 16;
    size_t o = (((size_t)(b * HEADS + h)) * NKV_PAD + 1024 + s) * DK + d;
    if (s < MSLOT) {
        g_k[o] = __float2half_rn(32.0f * m_k[s * DMODEL + h * 64 + d]);
        g_v[o] = __float2half_rn(2.8284271247461903f * m_v[s * DMODEL + h * 64 + d]);
    } else {
        g_k[o] = __float2half_rn(0.0f);
        g_v[o] = __float2half_rn(0.0f);
    }
}

// ------------------------- HMMA GEMM (BK=64, 2-stage double buffer) ---------
// Stage = A(128x64 fp16, 16KB) + B(128x64 fp16, 16KB), XOR-swizzled 128B rows.
static constexpr int TILE_BYTES = 128 * 128;         // 16KB per operand tile
static constexpr int STAGE_B = 2 * TILE_BYTES;       // 32KB
static constexpr int GEMM_SMEM = 2 * STAGE_B;        // 65536

template <int NT, int EPI>
__global__ void __launch_bounds__(256, 2) gemm_mma(const float* __restrict__ bias,
                                                   float* __restrict__ outp) {
    extern __shared__ __align__(128) char sm[];
    const uint32_t smb = s2u(sm);
    const int tid = threadIdx.x, warp = tid >> 5, lane = tid & 31;

    const int lin = blockIdx.y * gridDim.x + blockIdx.x;
    const int bandsz = gridDim.x * 8;
    const int band = lin / bandsz, rem = lin % bandsz;
    const int by = band * 8 + (rem & 7);
    const int bx = rem >> 3;
    const int rowbase = by * 128, colbase = bx * 128;
    const int wr = (warp >> 2) * 64, wc = (warp & 3) * 32;

    const __half *ah, *bhp;
    if (EPI == 0) {
        const int z = colbase >> 10;
        ah = g_inh + (size_t)z * 8388608;
        bhp = g_wh;
    } else {
        ah = g_aoh;
        bhp = g_woh;
    }

    float acc[4][4][4];
#pragma unroll
    for (int i = 0; i < 4; i++)
#pragma unroll
        for (int j = 0; j < 4; j++)
#pragma unroll
            for (int u = 0; u < 4; u++) acc[i][j][u] = 0.0f;

    auto issue = [&](int kt) {
        const int slot = kt & 1;
        const int k0 = kt << 6;   // 64 halves per k-tile
        const __half* Ag = ah + (size_t)rowbase * 1024 + k0;
        const __half* Bg = bhp + (size_t)colbase * 1024 + k0;
        const uint32_t dstS = smb + slot * STAGE_B;
#pragma unroll
        for (int c8 = 0; c8 < 8; c8++) {
            int idx = tid + c8 * 256;            // 2048 x 16B chunks
            int isB = idx >> 10;
            int e = idx & 1023;
            int r = e >> 3, c = e & 7;           // 128 rows x 8 chunks
            const __half* src = (isB ? Bg : Ag) + (size_t)r * 1024 + c * 8;
            uint32_t dst = dstS + isB * TILE_BYTES + r * 128 + ((c ^ (r & 7)) * 16);
            cpasync16(dst, src);
        }
    };

    issue(0);
    asm volatile("cp.async.commit_group;" ::: "memory");

    for (int kt = 0; kt < NT; kt++) {
        // write slot (kt+1)&1 = slot of kt-1; its readers finished before the
        // trailing sync of iter kt-1, which every warp has passed.
        if (kt + 1 < NT) issue(kt + 1);
        asm volatile("cp.async.commit_group;" ::: "memory");
        asm volatile("cp.async.wait_group 1;" ::: "memory");
        __syncthreads();

        const uint32_t aBase = smb + (kt & 1) * STAGE_B;
        const uint32_t bBase = aBase + TILE_BYTES;
#pragma unroll
        for (int k16 = 0; k16 < 4; k16++) {
            uint32_t a[4][4];
#pragma unroll
            for (int mt = 0; mt < 4; mt++) {
                int r = wr + mt * 16 + (lane & 15);
                int cc = k16 * 2 + (lane >> 4);
                LDM_X4(a[mt], aBase + r * 128 + ((cc ^ (r & 7)) * 16));
            }
            uint32_t b[2][4];
#pragma unroll
            for (int bt = 0; bt < 2; bt++) {
                int r = wc + bt * 16 + (lane & 7) + ((lane >> 4) & 1) * 8;
                int cc = k16 * 2 + ((lane >> 3) & 1);
                LDM_X4(b[bt], bBase + r * 128 + ((cc ^ (r & 7)) * 16));
            }
#pragma unroll
            for (int mt = 0; mt < 4; mt++)
#pragma unroll
                for (int nt = 0; nt < 4; nt++)
                    mma16816(acc[mt][nt], a[mt], b[nt >> 1][(nt & 1) * 2],
                             b[nt >> 1][(nt & 1) * 2 + 1]);
        }
        __syncthreads();
    }

    const int r0 = lane >> 2, cp = (lane & 3) * 2;
#pragma unroll
    for (int mt = 0; mt < 4; mt++) {
#pragma unroll
        for (int nt = 0; nt < 4; nt++) {
            const float* cc = acc[mt][nt];
            int gr = rowbase + wr + mt * 16 + r0;
            int gc = colbase + wc + nt * 8 + cp;
            if (EPI == 0) {
                const int z = gc >> 10;
                __half* dst = (z == 0) ? g_q : (z == 1) ? g_k : g_v;
                const int L = (z == 0) ? NQ : NKV_PAD;
                float b0 = __half2float(__float2half_rn(bias[gc]));
                float b1 = __half2float(__float2half_rn(bias[gc + 1]));
                int cz = gc & 1023;
                int hh = cz >> 6, dk = cz & 63;
#pragma unroll
                for (int rh = 0; rh < 2; rh++) {
                    int g = gr + rh * 8;
                    int n = g >> 3, bb = g & 7;
                    size_t o = (((size_t)(bb * HEADS + hh)) * L + n) * 64 + dk;
                    __half hv[2] = {__float2half_rn(cc[rh * 2] + b0),
                                    __float2half_rn(cc[rh * 2 + 1] + b1)};
                    *(uint32_t*)&dst[o] = *(uint32_t*)hv;
                }
            } else {
                float b0 = bias[gc], b1 = bias[gc + 1];
#pragma unroll
                for (int rh = 0; rh < 2; rh++) {
                    int g = gr + rh * 8;
                    float2 v = make_float2(cc[rh * 2] + b0, cc[rh * 2 + 1] + b1);
                    *(float2*)&outp[(size_t)g * 1024 + gc] = v;
                }
            }
        }
    }
}

// ------------------------- flash attention (reg FA2, 3-stage, 1 sync) -------
static constexpr int ATTN_SMEM = 16384 + 3 * 16384;   // Q + 3 KV stages

__global__ void __launch_bounds__(256, 2) attn_kernel(const float* __restrict__ mask) {
    extern __shared__ __align__(128) char smc[];
    const uint32_t smb = s2u(smc);
    const int tid = threadIdx.x, warp = tid >> 5, lane = tid & 31;
    const int qt = blockIdx.x, bh = blockIdx.y;
    const int q0 = qt * 128;
    const __half* qg = g_q + ((size_t)bh * NQ + q0) * DK;
    const __half* kg = g_k + (size_t)bh * NKV_PAD * DK;
    const __half* vg = g_v + (size_t)bh * NKV_PAD * DK;

    auto issueKV = [&](int t) {
        const uint32_t base = smb + 16384 + (t % 3) * 16384;
        const __half* kp = kg + (size_t)t * 64 * 64;
        const __half* vp = vg + (size_t)t * 64 * 64;
#pragma unroll
        for (int it = 0; it < 2; it++) {
            int idx = tid + it * 256;
            int r = idx >> 3, c = idx & 7;
            uint32_t so = r * 128 + ((c ^ (r & 7)) * 16);
            cpasync16(base + so, kp + (size_t)r * 64 + c * 8);
            cpasync16(base + 8192 + so, vp + (size_t)r * 64 + c * 8);
        }
    };

    issueKV(0);
    asm volatile("cp.async.commit_group;" ::: "memory");
    issueKV(1);
    asm volatile("cp.async.commit_group;" ::: "memory");

#pragma unroll
    for (int it = 0; it < 4; it++) {
        int idx = tid + it * 256;
        int r = idx >> 3, c = idx & 7;
        *(uint4*)(smc + r * 128 + ((c ^ (r & 7)) * 16)) =
            *(const uint4*)(qg + (size_t)r * 64 + c * 8);
    }
    __syncthreads();

    uint32_t qa[4][4];
    {
        const __half2 sc8 = __floats2half2_rn(0.125f, 0.125f);
        int r = warp * 16 + (lane & 7) + ((lane >> 3) & 1) * 8;
#pragma unroll
        for (int u = 0; u < 4; u++) {
            int c = u * 2 + (lane >> 4);
            LDM_X4(qa[u], smb + r * 128 + ((c ^ (r & 7)) * 16));
#pragma unroll
            for (int j = 0; j < 4; j++) {
                __half2 h = __hmul2(*(__half2*)&qa[u][j], sc8);
                qa[u][j] = *(uint32_t*)&h;
            }
        }
    }

    float o[8][4];
#pragma unroll
    for (int n = 0; n < 8; n++)
#pragma unroll
        for (int j = 0; j < 4; j++) o[n][j] = 0.0f;
    float mprevA = -1e30f, mprevB = -1e30f, laccA = 0.0f, laccB = 0.0f;

    const int rA = lane >> 2;
    const float* mrowA = mask + ((size_t)bh * NQ + q0 + warp * 16 + rA) * NQ +
                         2 * (lane & 3);
    const float* mrowB = mrowA + 8 * NQ;

    for (int t = 0; t < 17; t++) {
        asm volatile("cp.async.wait_group 1;" ::: "memory");
        __syncthreads();

        const uint32_t kb = smb + 16384 + (t % 3) * 16384;
        const uint32_t vb = kb + 8192;

        float s[8][4];
        if (t < 16) {
            const float* mA = mrowA + t * 64;
            const float* mB = mrowB + t * 64;
#pragma unroll
            for (int n = 0; n < 8; n++) {
                float2 xa = *(const float2*)(mA + n * 8);
                float2 xb = *(const float2*)(mB + n * 8);
                s[n][0] = xa.x; s[n][1] = xa.y;
                s[n][2] = xb.x; s[n][3] = xb.y;
            }
        } else {
            s[0][0] = s[0][1] = s[0][2] = s[0][3] = 0.0f;
#pragma unroll
            for (int n = 1; n < 8; n++)
                s[n][0] = s[n][1] = s[n][2] = s[n][3] = -1e30f;
        }

        {
            const int rn = (lane & 7) + ((lane >> 4) & 1) * 8;
            const int ck = (lane >> 3) & 1;
#pragma unroll
            for (int g = 0; g < 4; g++) {
                int r = g * 16 + rn;
#pragma unroll
                for (int u = 0; u < 4; u++) {
                    int c = u * 2 + ck;
                    uint32_t kb4[4];
                    LDM_X4(kb4, kb + r * 128 + ((c ^ (r & 7)) * 16));
                    mma16816(s[2 * g],     qa[u], kb4[0], kb4[1]);
                    mma16816(s[2 * g + 1], qa[u], kb4[2], kb4[3]);
                }
            }
        }

        float mxA = -1e30f, mxB = -1e30f;
#pragma unroll
        for (int n = 0; n < 8; n++) {
            mxA = fmaxf(mxA, fmaxf(s[n][0], s[n][1]));
            mxB = fmaxf(mxB, fmaxf(s[n][2], s[n][3]));
        }
        mxA = fmaxf(mxA, __shfl_xor_sync(0xffffffffu, mxA, 1));
        mxA = fmaxf(mxA, __shfl_xor_sync(0xffffffffu, mxA, 2));
        mxB = fmaxf(mxB, __shfl_xor_sync(0xffffffffu, mxB, 1));
        mxB = fmaxf(mxB, __shfl_xor_sync(0xffffffffu, mxB, 2));
        float mnA = fmaxf(mprevA, mxA), mnB = fmaxf(mprevB, mxB);
        float aA = __expf(mprevA - mnA), aB = __expf(mprevB - mnB);
        mprevA = mnA; mprevB = mnB;

        uint32_t pf[4][4];
        float sumA = 0.0f, sumB = 0.0f;
#pragma unroll
        for (int n = 0; n < 8; n++) {
            float p0 = __expf(s[n][0] - mnA);
            float p1 = __expf(s[n][1] - mnA);
            float p2 = __expf(s[n][2] - mnB);
            float p3 = __expf(s[n][3] - mnB);
            sumA += p0 + p1; sumB += p2 + p3;
            pf[n >> 1][(n & 1) * 2]     = packh2(p0, p1);
            pf[n >> 1][(n & 1) * 2 + 1] = packh2(p2, p3);
        }
        sumA += __shfl_xor_sync(0xffffffffu, sumA, 1);
        sumA += __shfl_xor_sync(0xffffffffu, sumA, 2);
        sumB += __shfl_xor_sync(0xffffffffu, sumB, 1);
        sumB += __shfl_xor_sync(0xffffffffu, sumB, 2);
        laccA = laccA * aA + sumA;
        laccB = laccB * aB + sumB;
#pragma unroll
        for (int n = 0; n < 8; n++) {
            o[n][0] *= aA; o[n][1] *= aA;
            o[n][2] *= aB; o[n][3] *= aB;
        }

        {
            int rr = (lane & 7) + ((lane >> 3) & 1) * 8;
#pragma unroll
            for (int u = 0; u < 4; u++) {
                int r = u * 16 + rr;
#pragma unroll
                for (int dp = 0; dp < 4; dp++) {
                    int c = dp * 2 + (lane >> 4);
                    uint32_t vb4[4];
                    LDM_X4_T(vb4, vb + r * 128 + ((c ^ (r & 7)) * 16));
                    mma16816(o[2 * dp],     pf[u], vb4[0], vb4[1]);
                    mma16816(o[2 * dp + 1], pf[u], vb4[2], vb4[3]);
                }
            }
        }

        if (t + 2 < 17) issueKV(t + 2);
        asm volatile("cp.async.commit_group;" ::: "memory");
    }

    const int b = bh >> 4, h = bh & 15;
    const int qrA = q0 + warp * 16 + rA;
    const float invA = 1.0f / laccA, invB = 1.0f / laccB;
#pragma unroll
    for (int n = 0; n < 8; n++) {
        int dk = h * 64 + n * 8 + 2 * (lane & 3);
        {
            __half hv[2] = {__float2half_rn(o[n][0] * invA),
                            __float2half_rn(o[n][1] * invA)};
            *(uint32_t*)&g_aoh[((size_t)qrA * BATCH + b) * DMODEL + dk] =
                *(uint32_t*)hv;
        }
        {
            __half hv[2] = {__float2half_rn(o[n][2] * invB),
                            __float2half_rn(o[n][3] * invB)};
            *(uint32_t*)&g_aoh[((size_t)(qrA + 8) * BATCH + b) * DMODEL + dk] =
                *(uint32_t*)hv;
        }
    }
}

// ------------------------- launch -------------------------------------------
extern "C" void kernel_launch(void* const* d_in, const int* in_sizes, int n_in,
                              void* d_out, int out_size) {
    const float* queries = (const float*)d_in[0];
    const float* keys    = (const float*)d_in[1];
    const float* values  = (const float*)d_in[2];
    const float* m_k     = (const float*)d_in[3];
    const float* m_v     = (const float*)d_in[4];
    const float* mask    = (const float*)d_in[5];
    const float* in_w    = (const float*)d_in[6];
    const float* in_b    = (const float*)d_in[7];
    const float* out_w   = (const float*)d_in[8];
    const float* out_b   = (const float*)d_in[9];
    float* out = (float*)d_out;
    (void)in_sizes; (void)n_in; (void)out_size;

    cudaFuncSetAttribute(attn_kernel, cudaFuncAttributeMaxDynamicSharedMemorySize,
                         ATTN_SMEM);
    cudaFuncSetAttribute(gemm_mma<16, 0>, cudaFuncAttributeMaxDynamicSharedMemorySize,
                         GEMM_SMEM);
    cudaFuncSetAttribute(gemm_mma<16, 1>, cudaFuncAttributeMaxDynamicSharedMemorySize,
                         GEMM_SMEM);

    convert_kernel<<<28672, 256>>>(queries, keys, values, in_w, out_w);
    fill_mem_kernel<<<2048, 256>>>(m_k, m_v);
    gemm_mma<16, 0><<<dim3(24, 64), 256, GEMM_SMEM>>>(in_b, nullptr);  // QKV proj
    attn_kernel<<<dim3(8, 128), 256, ATTN_SMEM>>>(mask);
    gemm_mma<16, 1><<<dim3(8, 64), 256, GEMM_SMEM>>>(out_b, out);      // out proj
}